// round 13
// baseline (speedup 1.0000x reference)
#include <cuda_runtime.h>
#include <cuda_bf16.h>
#include <stdint.h>

// Problem constants
#define BB 4
#define SS 2048
#define DD 1024
#define HH 16
#define HD 64
#define BS (BB*SS)
#define NQ (BB*HH*SS*HD)
#define NX (BS*DD)
#define NW (DD*DD)

// ---------------------------------------------------------------------------
// Static device scratch
// ---------------------------------------------------------------------------
__device__ __nv_bfloat16 g_xhi[NX],  g_xlo[NX];
__device__ __nv_bfloat16 g_ahi[NX],  g_alo[NX];       // attention out hi/lo
__device__ __nv_bfloat16 g_qhi[NQ],  g_qlo[NQ];
__device__ __nv_bfloat16 g_khi[NQ],  g_klo[NQ];
__device__ __nv_bfloat16 g_vthi[NQ], g_vtlo[NQ];      // [B,H,HD,S]
__device__ __nv_bfloat16 g_wh[4][NW], g_wl[4][NW];

// ---------------------------------------------------------------------------
// helpers
// ---------------------------------------------------------------------------
__device__ __forceinline__ uint32_t pack_bf2(float a, float b) {
    __nv_bfloat16 ha = __float2bfloat16(a), hb = __float2bfloat16(b);
    unsigned short ua = *reinterpret_cast<unsigned short*>(&ha);
    unsigned short ub = *reinterpret_cast<unsigned short*>(&hb);
    return (uint32_t)ua | ((uint32_t)ub << 16);
}
__device__ __forceinline__ float bf_res(float x) {
    __nv_bfloat16 h = __float2bfloat16(x);
    return x - __bfloat162float(h);
}

__device__ __forceinline__ void mma_bf16(float* c, const uint32_t* a,
                                         uint32_t b0, uint32_t b1)
{
    asm("mma.sync.aligned.m16n8k16.row.col.f32.bf16.bf16.f32 "
        "{%0,%1,%2,%3},{%4,%5,%6,%7},{%8,%9},{%0,%1,%2,%3};"
        : "+f"(c[0]), "+f"(c[1]), "+f"(c[2]), "+f"(c[3])
        : "r"(a[0]), "r"(a[1]), "r"(a[2]), "r"(a[3]), "r"(b0), "r"(b1));
}

__device__ __forceinline__ void ldsm_x4(uint32_t* r, uint32_t addr) {
    asm volatile("ldmatrix.sync.aligned.m8n8.x4.shared.b16 {%0,%1,%2,%3}, [%4];"
        : "=r"(r[0]), "=r"(r[1]), "=r"(r[2]), "=r"(r[3]) : "r"(addr));
}

#define CP16(dst_smem_u32, src_gptr) \
    asm volatile("cp.async.cg.shared.global [%0], [%1], 16;\n" \
                 :: "r"(dst_smem_u32), "l"(src_gptr))
#define CP_COMMIT() asm volatile("cp.async.commit_group;\n")
#define CP_WAIT1()  asm volatile("cp.async.wait_group 1;\n")
#define CP_WAIT0()  asm volatile("cp.async.wait_group 0;\n")

// ---------------------------------------------------------------------------
// merged split: x (NX/4 float4s) then 4 weights (NW/4 each) in one launch
// ---------------------------------------------------------------------------
__global__ __launch_bounds__(256) void split_all_kernel(
    const float* __restrict__ x,
    const float* __restrict__ W0, const float* __restrict__ W1,
    const float* __restrict__ W2, const float* __restrict__ W3,
    __nv_bfloat16* __restrict__ xhi, __nv_bfloat16* __restrict__ xlo,
    __nv_bfloat16* __restrict__ wh,  __nv_bfloat16* __restrict__ wl)
{
    const int gi = blockIdx.x * 256 + threadIdx.x;   // < NX/4 + NW  (3145728)
    const float* src;
    __nv_bfloat16 *hi, *lo;
    size_t o;
    if (gi < NX/4) {
        src = x; hi = xhi; lo = xlo; o = gi;
        float4 v = ((const float4*)src)[o];
        ((uint2*)hi)[o] = make_uint2(pack_bf2(v.x, v.y), pack_bf2(v.z, v.w));
        ((uint2*)lo)[o] = make_uint2(pack_bf2(bf_res(v.x), bf_res(v.y)),
                                     pack_bf2(bf_res(v.z), bf_res(v.w)));
    } else {
        const int wi = gi - NX/4;            // < NW (4 * NW/4)
        const int z  = wi >> 18;             // / (NW/4 = 262144)
        const int j  = wi & 262143;
        src = (z == 0) ? W0 : (z == 1) ? W1 : (z == 2) ? W2 : W3;
        float4 v = ((const float4*)src)[j];
        o = (size_t)z * (NW/4) + j;
        ((uint2*)wh)[o] = make_uint2(pack_bf2(v.x, v.y), pack_bf2(v.z, v.w));
        ((uint2*)wl)[o] = make_uint2(pack_bf2(bf_res(v.x), bf_res(v.y)),
                                     pack_bf2(bf_res(v.z), bf_res(v.w)));
    }
}
#define SPLIT_BLOCKS ((NX/4 + NW) / 256)     // 12288

// ---------------------------------------------------------------------------
// bf16x3 GEMM mainloop — tile 128(M) x 256(N) x 32(K), 512 threads, 16 warps
// (4m x 4n, warp tile 32x64 — per-warp code identical to proven version).
// Single barrier per K-iteration.
// ---------------------------------------------------------------------------
#define RST 20
#define OPBA (128*RST)          // A buffer u32 (2560)
#define OPBW (256*RST)          // W buffer u32 (5120)
#define STGU (2*OPBA + 2*OPBW)  // stage u32 (15360)
#define GEMM_SMEM (2*STGU*4)    // 122880 B

__device__ __forceinline__ void gemm_mainloop(
    const __nv_bfloat16* __restrict__ Ah, const __nv_bfloat16* __restrict__ Al,
    const __nv_bfloat16* __restrict__ Wh, const __nv_bfloat16* __restrict__ Wl,
    int m0, int n0, uint32_t smb, int tid, float acc[2][8][4])
{
    const int lane = tid & 31;
    const int w    = tid >> 5;              // 0..15
    const int wm   = (w & 3) * 32;
    const int wn   = (w >> 2) * 64;
    const uint32_t aoff = (uint32_t)(((((lane>>3)&1)*8 + (lane&7))*RST + ((lane>>4)*4)) * 4);
    const uint32_t boff = (uint32_t)((((lane>>4)*8 + (lane&7))*RST + (((lane>>3)&1)*4)) * 4);

    const int NK = DD / 32;

    #define LOAD_STAGE(kt, stg) do {                                          \
        uint32_t sb_ = smb + (stg)*STGU*4;                                    \
        {   /* A: 512 chunks hi + 512 lo; one each per thread */              \
            int row_ = tid >> 2, c16_ = tid & 3;                              \
            uint32_t so_ = sb_ + (uint32_t)((row_*RST + c16_*4)*4);           \
            size_t ga_ = (size_t)(m0+row_)*DD + (kt)*32 + c16_*8;             \
            CP16(so_,          Ah + ga_);                                     \
            CP16(so_ + OPBA*4, Al + ga_);                                     \
        }                                                                     \
        _Pragma("unroll")                                                     \
        for (int i_ = 0; i_ < 2; i_++) {   /* W: 1024 chunks hi + 1024 lo */  \
            int c_ = tid + 512*i_;                                            \
            int row_ = c_ >> 2, c16_ = c_ & 3;                                \
            uint32_t so_ = sb_ + 2*OPBA*4 + (uint32_t)((row_*RST + c16_*4)*4);\
            size_t gw_ = (size_t)(n0+row_)*DD + (kt)*32 + c16_*8;             \
            CP16(so_,          Wh + gw_);                                     \
            CP16(so_ + OPBW*4, Wl + gw_);                                     \
        }                                                                     \
        CP_COMMIT();                                                          \
    } while (0)

    LOAD_STAGE(0, 0);

    for (int it = 0; it < NK; it++) {
        CP_WAIT0();
        __syncthreads();
        if (it + 1 < NK)
            LOAD_STAGE(it + 1, (it + 1) & 1);

        const uint32_t sb  = smb + (it & 1)*STGU*4;
        const uint32_t ahB = sb;
        const uint32_t alB = sb + OPBA*4;
        const uint32_t whB = sb + 2*OPBA*4;
        const uint32_t wlB = whB + OPBW*4;

        #pragma unroll
        for (int s16 = 0; s16 < 2; s16++) {
            const uint32_t kbyte = s16 * 32;
            uint32_t ah[2][4], al[2][4];
            #pragma unroll
            for (int mt = 0; mt < 2; mt++) {
                const uint32_t ro = (uint32_t)((wm + mt*16)*RST*4);
                ldsm_x4(ah[mt], ahB + aoff + ro + kbyte);
                ldsm_x4(al[mt], alB + aoff + ro + kbyte);
            }
            #pragma unroll
            for (int ntp = 0; ntp < 4; ntp++) {
                const uint32_t ro = (uint32_t)((wn + ntp*16)*RST*4);
                uint32_t wh4[4], wl4[4];
                ldsm_x4(wh4, whB + boff + ro + kbyte);
                ldsm_x4(wl4, wlB + boff + ro + kbyte);
                #pragma unroll
                for (int j = 0; j < 2; j++) {
                    const int nt = 2*ntp + j;
                    const uint32_t bh0 = wh4[2*j], bh1 = wh4[2*j+1];
                    const uint32_t bl0 = wl4[2*j], bl1 = wl4[2*j+1];
                    #pragma unroll
                    for (int mt = 0; mt < 2; mt++) {
                        mma_bf16(acc[mt][nt], ah[mt], bh0, bh1);
                        mma_bf16(acc[mt][nt], ah[mt], bl0, bl1);
                        mma_bf16(acc[mt][nt], al[mt], bh0, bh1);
                    }
                }
            }
        }
    }
    #undef LOAD_STAGE
}

// ---------------------------------------------------------------------------
// QKV merged GEMM: grid = (DD/256, BS/128, 3); z: 0=Q rope, 1=K rope, 2=V t-split
// ---------------------------------------------------------------------------
__global__ __launch_bounds__(512, 1) void gemm_qkv_kernel(
    const __nv_bfloat16* __restrict__ Ah, const __nv_bfloat16* __restrict__ Al,
    const __nv_bfloat16* __restrict__ whAll, const __nv_bfloat16* __restrict__ wlAll,
    const float* __restrict__ bq, const float* __restrict__ bk,
    const float* __restrict__ bv,
    const float* __restrict__ cosb, const float* __restrict__ sinb,
    __nv_bfloat16* __restrict__ Qhi, __nv_bfloat16* __restrict__ Qlo,
    __nv_bfloat16* __restrict__ Khi, __nv_bfloat16* __restrict__ Klo,
    __nv_bfloat16* __restrict__ Vthi, __nv_bfloat16* __restrict__ Vtlo)
{
    extern __shared__ uint32_t su[];
    const uint32_t smb = (uint32_t)__cvta_generic_to_shared(su);
    const int tid = threadIdx.x;
    const int m0  = blockIdx.y * 128;
    const int n0  = blockIdx.x * 256;
    const int z   = blockIdx.z;

    const __nv_bfloat16* Wh = whAll + (size_t)z * NW;
    const __nv_bfloat16* Wl = wlAll + (size_t)z * NW;
    const float* bias = (z == 0) ? bq : (z == 1) ? bk : bv;

    float acc[2][8][4];
    #pragma unroll
    for (int mt = 0; mt < 2; mt++)
        #pragma unroll
        for (int nt = 0; nt < 8; nt++)
            #pragma unroll
            for (int r = 0; r < 4; r++) acc[mt][nt][r] = 0.f;

    gemm_mainloop(Ah, Al, Wh, Wl, m0, n0, smb, tid, acc);

    const int lane = tid & 31;
    const int w    = tid >> 5;
    const int g    = lane >> 2;
    const int q    = lane & 3;
    const int wm   = (w & 3) * 32;
    const int wn   = (w >> 2) * 64;

    if (z < 2) {
        __nv_bfloat16* ChiT = (z == 0) ? Qhi : Khi;
        __nv_bfloat16* CloT = (z == 0) ? Qlo : Klo;
        uint32_t* HI = (uint32_t*)ChiT;
        uint32_t* LO = (uint32_t*)CloT;
        #pragma unroll
        for (int mt = 0; mt < 2; mt++) {
            const int row0 = m0 + wm + mt*16 + g;
            #pragma unroll
            for (int nt = 0; nt < 4; nt++) {
                const int col = n0 + wn + nt*8 + 2*q;
                const int d = col & 63, h = col >> 6;
                const float bi10 = bias[col],    bi11 = bias[col+1];
                const float bi20 = bias[col+32], bi21 = bias[col+33];
                #pragma unroll
                for (int r2 = 0; r2 < 2; r2++) {
                    const int row = row0 + r2*8;
                    const int b_ = row >> 11, s_ = row & 2047;
                    const float2 cs1 = *(const float2*)&cosb[s_*HD + d];
                    const float2 sn1 = *(const float2*)&sinb[s_*HD + d];
                    const float2 cs2 = *(const float2*)&cosb[s_*HD + d + 32];
                    const float2 sn2 = *(const float2*)&sinb[s_*HD + d + 32];
                    const float x10 = acc[mt][nt  ][r2*2+0] + bi10;
                    const float x11 = acc[mt][nt  ][r2*2+1] + bi11;
                    const float x20 = acc[mt][nt+4][r2*2+0] + bi20;
                    const float x21 = acc[mt][nt+4][r2*2+1] + bi21;
                    const float o10 = x10*cs1.x - x20*sn1.x;
                    const float o11 = x11*cs1.y - x21*sn1.y;
                    const float o20 = x20*cs2.x + x10*sn2.x;
                    const float o21 = x21*cs2.y + x11*sn2.y;
                    const size_t base = (((size_t)b_*HH + h)*SS + s_)*HD;
                    HI[(base + d     ) >> 1] = pack_bf2(o10, o11);
                    LO[(base + d     ) >> 1] = pack_bf2(bf_res(o10), bf_res(o11));
                    HI[(base + d + 32) >> 1] = pack_bf2(o20, o21);
                    LO[(base + d + 32) >> 1] = pack_bf2(bf_res(o20), bf_res(o21));
                }
            }
        }
    } else {
        // V: direct transposed split write [B,H,HD,S]
        #pragma unroll
        for (int mt = 0; mt < 2; mt++) {
            const int row0 = m0 + wm + mt*16 + g;
            #pragma unroll
            for (int nt = 0; nt < 8; nt++) {
                const int col = n0 + wn + nt*8 + 2*q;
                const int h = col >> 6, d = col & 63;
                const float b0 = bias[col], b1 = bias[col+1];
                #pragma unroll
                for (int r2 = 0; r2 < 2; r2++) {
                    const int row = row0 + r2*8;
                    const int b_ = row >> 11, s_ = row & 2047;
                    const float v0 = acc[mt][nt][r2*2+0] + b0;
                    const float v1 = acc[mt][nt][r2*2+1] + b1;
                    const size_t base0 = (((size_t)b_*HH + h)*HD + d)*SS + s_;
                    Vthi[base0]      = __float2bfloat16(v0);
                    Vtlo[base0]      = __float2bfloat16(bf_res(v0));
                    Vthi[base0 + SS] = __float2bfloat16(v1);
                    Vtlo[base0 + SS] = __float2bfloat16(bf_res(v1));
                }
            }
        }
    }
}

// ---------------------------------------------------------------------------
// Output-projection GEMM: plain fp32 out [M,N]
// ---------------------------------------------------------------------------
__global__ __launch_bounds__(512, 1) void gemm_out_kernel(
    const __nv_bfloat16* __restrict__ Ah, const __nv_bfloat16* __restrict__ Al,
    const __nv_bfloat16* __restrict__ Wh, const __nv_bfloat16* __restrict__ Wl,
    const float* __restrict__ bias, float* __restrict__ Cf)
{
    extern __shared__ uint32_t su[];
    const uint32_t smb = (uint32_t)__cvta_generic_to_shared(su);
    const int tid = threadIdx.x;
    const int m0  = blockIdx.y * 128;
    const int n0  = blockIdx.x * 256;

    float acc[2][8][4];
    #pragma unroll
    for (int mt = 0; mt < 2; mt++)
        #pragma unroll
        for (int nt = 0; nt < 8; nt++)
            #pragma unroll
            for (int r = 0; r < 4; r++) acc[mt][nt][r] = 0.f;

    gemm_mainloop(Ah, Al, Wh, Wl, m0, n0, smb, tid, acc);

    const int lane = tid & 31;
    const int w    = tid >> 5;
    const int g    = lane >> 2;
    const int q    = lane & 3;
    const int wm   = (w & 3) * 32;
    const int wn   = (w >> 2) * 64;

    #pragma unroll
    for (int mt = 0; mt < 2; mt++) {
        const int row0 = m0 + wm + mt*16 + g;
        const int row1 = row0 + 8;
        #pragma unroll
        for (int nt = 0; nt < 8; nt++) {
            const int col = n0 + wn + nt*8 + 2*q;
            const float b0 = bias[col], b1 = bias[col + 1];
            *(float2*)&Cf[(size_t)row0*DD + col] =
                make_float2(acc[mt][nt][0] + b0, acc[mt][nt][1] + b1);
            *(float2*)&Cf[(size_t)row1*DD + col] =
                make_float2(acc[mt][nt][2] + b0, acc[mt][nt][3] + b1);
        }
    }
}

// ---------------------------------------------------------------------------
// FlashAttention-2 (causal), bf16x3 — exact R12 kernel (proven 317us).
// ---------------------------------------------------------------------------
#define KST 36
#define ATILE (64*KST)
#define ASTG  (4*ATILE)
#define ATTN_SMEM (2*ASTG*4)

__device__ __forceinline__ void attn_prefetch(
    uint32_t sstage,
    const __nv_bfloat16* __restrict__ Kh, const __nv_bfloat16* __restrict__ Kl,
    const __nv_bfloat16* __restrict__ Vth, const __nv_bfloat16* __restrict__ Vtl,
    size_t hb, int bh, int k0, int tid)
{
    #pragma unroll
    for (int i = 0; i < 4; i++) {
        int c = tid + 128*i;
        int row = c >> 3, c16 = c & 7;
        uint32_t so = sstage + (uint32_t)((row*KST + c16*4)*4);
        size_t ko = hb + (size_t)(k0 + row)*HD + c16*8;
        CP16(so,             Kh + ko);
        CP16(so + ATILE*4,   Kl + ko);
        size_t vo = ((size_t)bh*HD + row)*SS + k0 + c16*8;
        CP16(so + 2*ATILE*4, Vth + vo);
        CP16(so + 3*ATILE*4, Vtl + vo);
    }
    CP_COMMIT();
}

__global__ __launch_bounds__(128) void attn_bf3_kernel(
    const __nv_bfloat16* __restrict__ Qh, const __nv_bfloat16* __restrict__ Ql,
    const __nv_bfloat16* __restrict__ Kh, const __nv_bfloat16* __restrict__ Kl,
    const __nv_bfloat16* __restrict__ Vth, const __nv_bfloat16* __restrict__ Vtl,
    __nv_bfloat16* __restrict__ OutHi, __nv_bfloat16* __restrict__ OutLo)
{
    extern __shared__ uint32_t su[];
    const uint32_t smb = (uint32_t)__cvta_generic_to_shared(su);

    const int tid  = threadIdx.x;
    const int w    = tid >> 5;
    const int lane = tid & 31;
    const int g    = lane >> 2;
    const int q    = lane & 3;
    const int qt   = (SS/64 - 1) - blockIdx.x;
    const int bh   = blockIdx.y;
    const int q0   = qt * 64;
    const size_t hb = (size_t)bh * SS * HD;

    const uint32_t aoff = (uint32_t)(((((lane>>3)&1)*8 + (lane&7))*KST + ((lane>>4)*4)) * 4);
    const uint32_t boff = (uint32_t)((((lane>>4)*8 + (lane&7))*KST + (((lane>>3)&1)*4)) * 4);

    #pragma unroll
    for (int i = 0; i < 4; i++) {
        int c = tid + 128*i;
        int row = c >> 3, c16 = c & 7;
        uint32_t so = smb + ASTG*4 + (uint32_t)((row*KST + c16*4)*4);
        size_t go = hb + (size_t)(q0 + row)*HD + c16*8;
        CP16(so,           Qh + go);
        CP16(so + ATILE*4, Ql + go);
    }
    CP_COMMIT();
    attn_prefetch(smb, Kh, Kl, Vth, Vtl, hb, bh, 0, tid);

    CP_WAIT1();
    __syncthreads();

    const int rb = 16*w;
    uint32_t rQh[4][4], rQl[4][4];
    #pragma unroll
    for (int ks = 0; ks < 4; ks++) {
        const uint32_t ro = (uint32_t)(rb*KST*4) + ks*32;
        ldsm_x4(rQh[ks], smb + ASTG*4 + aoff + ro);
        ldsm_x4(rQl[ks], smb + ASTG*4 + ATILE*4 + aoff + ro);
    }
    __syncthreads();
    if (qt > 0)
        attn_prefetch(smb + ASTG*4, Kh, Kl, Vth, Vtl, hb, bh, 64, tid);

    float oc[8][4];
    #pragma unroll
    for (int nt = 0; nt < 8; nt++)
        #pragma unroll
        for (int r = 0; r < 4; r++) oc[nt][r] = 0.f;
    float m0 = -1e30f, m1 = -1e30f, l0 = 0.f, l1 = 0.f;

    const int row0g = q0 + 16*w + g;
    const int row1g = row0g + 8;

    for (int kt = 0; kt <= qt; kt++) {
        const int k0 = kt * 64;
        const uint32_t ab   = smb + (kt & 1)*ASTG*4;
        const uint32_t aKsH = ab;
        const uint32_t aKsL = ab + ATILE*4;
        const uint32_t aVsH = ab + 2*ATILE*4;
        const uint32_t aVsL = ab + 3*ATILE*4;

        if (kt < qt) { CP_WAIT1(); } else { CP_WAIT0(); }
        __syncthreads();

        float sc[8][4];
        #pragma unroll
        for (int nt = 0; nt < 8; nt++)
            #pragma unroll
            for (int r = 0; r < 4; r++) sc[nt][r] = 0.f;

        #pragma unroll
        for (int ks = 0; ks < 4; ks++) {
            const uint32_t kbyte = ks*32;
            #pragma unroll
            for (int ntp = 0; ntp < 4; ntp++) {
                const uint32_t ro = (uint32_t)(ntp*16*KST*4) + kbyte;
                uint32_t kh4[4], kl4[4];
                ldsm_x4(kh4, aKsH + boff + ro);
                ldsm_x4(kl4, aKsL + boff + ro);
                #pragma unroll
                for (int j = 0; j < 2; j++) {
                    const int nt = 2*ntp + j;
                    mma_bf16(sc[nt], rQh[ks], kh4[2*j], kh4[2*j+1]);
                    mma_bf16(sc[nt], rQh[ks], kl4[2*j], kl4[2*j+1]);
                    mma_bf16(sc[nt], rQl[ks], kh4[2*j], kh4[2*j+1]);
                }
            }
        }

        const float scale2 = 0.18033688f;   // 0.125 * log2(e)
        const bool diag = (kt == qt);
        #pragma unroll
        for (int nt = 0; nt < 8; nt++) {
            const int colb = k0 + nt*8 + 2*q;
            #pragma unroll
            for (int j = 0; j < 2; j++) {
                float v0 = sc[nt][j]   * scale2;
                float v1 = sc[nt][2+j] * scale2;
                if (diag && (colb + j) > row0g) v0 = -1e30f;
                if (diag && (colb + j) > row1g) v1 = -1e30f;
                sc[nt][j]   = v0;
                sc[nt][2+j] = v1;
            }
        }

        float mx0 = -1e30f, mx1 = -1e30f;
        #pragma unroll
        for (int nt = 0; nt < 8; nt++) {
            mx0 = fmaxf(mx0, fmaxf(sc[nt][0], sc[nt][1]));
            mx1 = fmaxf(mx1, fmaxf(sc[nt][2], sc[nt][3]));
        }
        mx0 = fmaxf(mx0, __shfl_xor_sync(0xffffffffu, mx0, 1));
        mx0 = fmaxf(mx0, __shfl_xor_sync(0xffffffffu, mx0, 2));
        mx1 = fmaxf(mx1, __shfl_xor_sync(0xffffffffu, mx1, 1));
        mx1 = fmaxf(mx1, __shfl_xor_sync(0xffffffffu, mx1, 2));
        const float mn0 = fmaxf(m0, mx0);
        const float mn1 = fmaxf(m1, mx1);
        const float a0 = exp2f(m0 - mn0);
        const float a1 = exp2f(m1 - mn1);
        m0 = mn0; m1 = mn1;

        uint32_t ph[8][2], pl[8][2];
        float s0 = 0.f, s1 = 0.f;
        #pragma unroll
        for (int nt = 0; nt < 8; nt++) {
            float p00 = exp2f(sc[nt][0] - mn0);
            float p01 = exp2f(sc[nt][1] - mn0);
            float p10 = exp2f(sc[nt][2] - mn1);
            float p11 = exp2f(sc[nt][3] - mn1);
            s0 += p00 + p01;
            s1 += p10 + p11;
            ph[nt][0] = pack_bf2(p00, p01);
            ph[nt][1] = pack_bf2(p10, p11);
            pl[nt][0] = pack_bf2(bf_res(p00), bf_res(p01));
            pl[nt][1] = pack_bf2(bf_res(p10), bf_res(p11));
        }
        s0 += __shfl_xor_sync(0xffffffffu, s0, 1);
        s0 += __shfl_xor_sync(0xffffffffu, s0, 2);
        s1 += __shfl_xor_sync(0xffffffffu, s1, 1);
        s1 += __shfl_xor_sync(0xffffffffu, s1, 2);
        l0 = l0*a0 + s0;
        l1 = l1*a1 + s1;
        #pragma unroll
        for (int nt = 0; nt < 8; nt++) {
            oc[nt][0] *= a0; oc[nt][1] *= a0;
            oc[nt][2] *= a1; oc[nt][3] *= a1;
        }

        #pragma unroll
        for (int kc = 0; kc < 4; kc++) {
            uint32_t ah4[4] = { ph[2*kc][0], ph[2*kc][1], ph[2*kc+1][0], ph[2*kc+1][1] };
            uint32_t al4[4] = { pl[2*kc][0], pl[2*kc][1], pl[2*kc+1][0], pl[2*kc+1][1] };
            const uint32_t kbyte = kc*32;
            #pragma unroll
            for (int ntp = 0; ntp < 4; ntp++) {
                const uint32_t ro = (uint32_t)(ntp*16*KST*4) + kbyte;
                uint32_t vh4[4], vl4[4];
                ldsm_x4(vh4, aVsH + boff + ro);
                ldsm_x4(vl4, aVsL + boff + ro);
                #pragma unroll
                for (int j = 0; j < 2; j++) {
                    const int nto = 2*ntp + j;
                    mma_bf16(oc[nto], ah4, vh4[2*j], vh4[2*j+1]);
                    mma_bf16(oc[nto], ah4, vl4[2*j], vl4[2*j+1]);
                    mma_bf16(oc[nto], al4, vh4[2*j], vh4[2*j+1]);
                }
            }
        }

        __syncthreads();
        if (kt + 2 <= qt)
            attn_prefetch(ab, Kh, Kl, Vth, Vtl, hb, bh, (kt + 2)*64, tid);
    }

    const float i0 = 1.f / l0;
    const float i1 = 1.f / l1;
    const int b = bh >> 4;
    const int h = bh & 15;
    const size_t o0 = ((size_t)(b*SS + row0g))*DD + h*HD;
    const size_t o1 = ((size_t)(b*SS + row1g))*DD + h*HD;
    uint32_t* HI = (uint32_t*)OutHi;
    uint32_t* LO = (uint32_t*)OutLo;
    #pragma unroll
    for (int nt = 0; nt < 8; nt++) {
        const int col = nt*8 + 2*q;
        const float v00 = oc[nt][0]*i0, v01 = oc[nt][1]*i0;
        const float v10 = oc[nt][2]*i1, v11 = oc[nt][3]*i1;
        HI[(o0 + col) >> 1] = pack_bf2(v00, v01);
        LO[(o0 + col) >> 1] = pack_bf2(bf_res(v00), bf_res(v01));
        HI[(o1 + col) >> 1] = pack_bf2(v10, v11);
        LO[(o1 + col) >> 1] = pack_bf2(bf_res(v10), bf_res(v11));
    }
}

// ---------------------------------------------------------------------------
// Launch
// ---------------------------------------------------------------------------
extern "C" void kernel_launch(void* const* d_in, const int* in_sizes, int n_in,
                              void* d_out, int out_size)
{
    const float* x    = (const float*)d_in[0];
    const float* cosb = (const float*)d_in[1];
    const float* sinb = (const float*)d_in[2];
    const float* Wq = (const float*)d_in[4];
    const float* bq = (const float*)d_in[5];
    const float* Wk = (const float*)d_in[6];
    const float* bk = (const float*)d_in[7];
    const float* Wv = (const float*)d_in[8];
    const float* bv = (const float*)d_in[9];
    const float* Wo = (const float*)d_in[10];
    const float* bo = (const float*)d_in[11];
    float* out = (float*)d_out;

    __nv_bfloat16 *xhi, *xlo, *ahi, *alo, *qhi, *qlo, *khi, *klo, *vthi, *vtlo;
    __nv_bfloat16 *wh, *wl;
    cudaGetSymbolAddress((void**)&xhi,  g_xhi);
    cudaGetSymbolAddress((void**)&xlo,  g_xlo);
    cudaGetSymbolAddress((void**)&ahi,  g_ahi);
    cudaGetSymbolAddress((void**)&alo,  g_alo);
    cudaGetSymbolAddress((void**)&qhi,  g_qhi);
    cudaGetSymbolAddress((void**)&qlo,  g_qlo);
    cudaGetSymbolAddress((void**)&khi,  g_khi);
    cudaGetSymbolAddress((void**)&klo,  g_klo);
    cudaGetSymbolAddress((void**)&vthi, g_vthi);
    cudaGetSymbolAddress((void**)&vtlo, g_vtlo);
    cudaGetSymbolAddress((void**)&wh,   g_wh);
    cudaGetSymbolAddress((void**)&wl,   g_wl);

    cudaFuncSetAttribute(gemm_qkv_kernel,
                         cudaFuncAttributeMaxDynamicSharedMemorySize, GEMM_SMEM);
    cudaFuncSetAttribute(gemm_out_kernel,
                         cudaFuncAttributeMaxDynamicSharedMemorySize, GEMM_SMEM);
    cudaFuncSetAttribute(attn_bf3_kernel,
                         cudaFuncAttributeMaxDynamicSharedMemorySize, ATTN_SMEM);

    split_all_kernel<<<SPLIT_BLOCKS, 256>>>(x, Wq, Wk, Wv, Wo,
                                            xhi, xlo, wh, wl);
    gemm_qkv_kernel<<<dim3(DD/256, BS/128, 3), 512, GEMM_SMEM>>>(
        xhi, xlo, wh, wl, bq, bk, bv, cosb, sinb,
        qhi, qlo, khi, klo, vthi, vtlo);
    attn_bf3_kernel<<<dim3(SS/64, BB*HH), 128, ATTN_SMEM>>>(
        qhi, qlo, khi, klo, vthi, vtlo, ahi, alo);
    gemm_out_kernel<<<dim3(DD/256, BS/128), 512, GEMM_SMEM>>>(
        ahi, alo, wh + 3*(size_t)NW, wl + 3*(size_t)NW, bo, out);
}

// round 14
// speedup vs baseline: 1.2992x; 1.2992x over previous
#include <cuda_runtime.h>
#include <cuda_bf16.h>
#include <cuda_fp16.h>
#include <stdint.h>

// Problem constants
#define BB 4
#define SS 2048
#define DD 1024
#define HH 16
#define HD 64
#define BS (BB*SS)
#define NQ (BB*HH*SS*HD)
#define NX (BS*DD)
#define NW (DD*DD)

// ---------------------------------------------------------------------------
// Static device scratch
// ---------------------------------------------------------------------------
__device__ __half g_xh[NX];                           // x as fp16 (single)
__device__ __half g_ah[NX];                           // attention out fp16 (single)
__device__ __half g_wh[4][NW], g_wl[4][NW];           // weights fp16 hi/lo
__device__ __nv_bfloat16 g_qhi[NQ],  g_qlo[NQ];
__device__ __nv_bfloat16 g_khi[NQ],  g_klo[NQ];
__device__ __nv_bfloat16 g_vthi[NQ], g_vtlo[NQ];      // [B,H,HD,S]

// ---------------------------------------------------------------------------
// helpers
// ---------------------------------------------------------------------------
__device__ __forceinline__ uint32_t pack_bf2(float a, float b) {
    __nv_bfloat16 ha = __float2bfloat16(a), hb = __float2bfloat16(b);
    unsigned short ua = *reinterpret_cast<unsigned short*>(&ha);
    unsigned short ub = *reinterpret_cast<unsigned short*>(&hb);
    return (uint32_t)ua | ((uint32_t)ub << 16);
}
__device__ __forceinline__ float bf_res(float x) {
    __nv_bfloat16 h = __float2bfloat16(x);
    return x - __bfloat162float(h);
}
__device__ __forceinline__ uint32_t pack_h2(float a, float b) {
    __half ha = __float2half_rn(a), hb = __float2half_rn(b);
    unsigned short ua = *reinterpret_cast<unsigned short*>(&ha);
    unsigned short ub = *reinterpret_cast<unsigned short*>(&hb);
    return (uint32_t)ua | ((uint32_t)ub << 16);
}
__device__ __forceinline__ float h_res(float x) {
    return x - __half2float(__float2half_rn(x));
}

__device__ __forceinline__ void mma_bf16(float* c, const uint32_t* a,
                                         uint32_t b0, uint32_t b1)
{
    asm("mma.sync.aligned.m16n8k16.row.col.f32.bf16.bf16.f32 "
        "{%0,%1,%2,%3},{%4,%5,%6,%7},{%8,%9},{%0,%1,%2,%3};"
        : "+f"(c[0]), "+f"(c[1]), "+f"(c[2]), "+f"(c[3])
        : "r"(a[0]), "r"(a[1]), "r"(a[2]), "r"(a[3]), "r"(b0), "r"(b1));
}
__device__ __forceinline__ void mma_f16(float* c, const uint32_t* a,
                                        uint32_t b0, uint32_t b1)
{
    asm("mma.sync.aligned.m16n8k16.row.col.f32.f16.f16.f32 "
        "{%0,%1,%2,%3},{%4,%5,%6,%7},{%8,%9},{%0,%1,%2,%3};"
        : "+f"(c[0]), "+f"(c[1]), "+f"(c[2]), "+f"(c[3])
        : "r"(a[0]), "r"(a[1]), "r"(a[2]), "r"(a[3]), "r"(b0), "r"(b1));
}

__device__ __forceinline__ void ldsm_x4(uint32_t* r, uint32_t addr) {
    asm volatile("ldmatrix.sync.aligned.m8n8.x4.shared.b16 {%0,%1,%2,%3}, [%4];"
        : "=r"(r[0]), "=r"(r[1]), "=r"(r[2]), "=r"(r[3]) : "r"(addr));
}

#define CP16(dst_smem_u32, src_gptr) \
    asm volatile("cp.async.cg.shared.global [%0], [%1], 16;\n" \
                 :: "r"(dst_smem_u32), "l"(src_gptr))
#define CP_COMMIT() asm volatile("cp.async.commit_group;\n")
#define CP_WAIT1()  asm volatile("cp.async.wait_group 1;\n")
#define CP_WAIT0()  asm volatile("cp.async.wait_group 0;\n")

// ---------------------------------------------------------------------------
// merged split: x -> fp16 single; 4 weights -> fp16 hi/lo
// ---------------------------------------------------------------------------
__global__ __launch_bounds__(256) void split_all_kernel(
    const float* __restrict__ x,
    const float* __restrict__ W0, const float* __restrict__ W1,
    const float* __restrict__ W2, const float* __restrict__ W3,
    __half* __restrict__ xh, __half* __restrict__ wh, __half* __restrict__ wl)
{
    const int gi = blockIdx.x * 256 + threadIdx.x;   // < NX/4 + NW
    if (gi < NX/4) {
        float4 v = ((const float4*)x)[gi];
        ((uint2*)xh)[gi] = make_uint2(pack_h2(v.x, v.y), pack_h2(v.z, v.w));
    } else {
        const int wi = gi - NX/4;
        const int z  = wi >> 18;             // / (NW/4 = 262144)
        const int j  = wi & 262143;
        const float* src = (z == 0) ? W0 : (z == 1) ? W1 : (z == 2) ? W2 : W3;
        float4 v = ((const float4*)src)[j];
        const size_t o = (size_t)z * (NW/4) + j;
        ((uint2*)wh)[o] = make_uint2(pack_h2(v.x, v.y), pack_h2(v.z, v.w));
        ((uint2*)wl)[o] = make_uint2(pack_h2(h_res(v.x), h_res(v.y)),
                                     pack_h2(h_res(v.z), h_res(v.w)));
    }
}
#define SPLIT_BLOCKS ((NX/4 + NW) / 256)     // 12288

// ---------------------------------------------------------------------------
// fp16x2 GEMM mainloop: C = A.W^T, A fp16 single-rounded, W fp16 hi/lo.
// 2 MMAs per k16 per acc (Ah*Wh + Ah*Wl). 128x128 tile, BK=32, 256 thr.
// Single barrier per K-iteration (R10/R12 proven structure).
// ---------------------------------------------------------------------------
#define RST 20
#define OPB (128*RST)            // per-buffer u32 (2560)
#define STGU (3*OPB)             // stage u32: A + Wh + Wl
#define GEMM_SMEM (2*STGU*4)     // 61440 B

__device__ __forceinline__ void gemm_mainloop(
    const __half* __restrict__ Ah,
    const __half* __restrict__ Wh, const __half* __restrict__ Wl,
    int m0, int n0, uint32_t smb, int tid, float acc[2][8][4])
{
    const int lane = tid & 31;
    const int w    = tid >> 5;
    const int wm   = (w & 3) * 32;
    const int wn   = (w >> 2) * 64;
    const uint32_t aoff = (uint32_t)(((((lane>>3)&1)*8 + (lane&7))*RST + ((lane>>4)*4)) * 4);
    const uint32_t boff = (uint32_t)((((lane>>4)*8 + (lane&7))*RST + (((lane>>3)&1)*4)) * 4);

    const int NK = DD / 32;

    #define LOAD_STAGE(kt, stg) do {                                          \
        uint32_t sb_ = smb + (stg)*STGU*4;                                    \
        _Pragma("unroll")                                                     \
        for (int i_ = 0; i_ < 2; i_++) {                                      \
            int c_ = tid + 256*i_;                                            \
            int row_ = c_ >> 2, c16_ = c_ & 3;                                \
            uint32_t so_ = sb_ + (uint32_t)((row_*RST + c16_*4)*4);           \
            size_t ga_ = (size_t)(m0+row_)*DD + (kt)*32 + c16_*8;             \
            size_t gw_ = (size_t)(n0+row_)*DD + (kt)*32 + c16_*8;             \
            CP16(so_,           Ah + ga_);                                    \
            CP16(so_ + OPB*4,   Wh + gw_);                                    \
            CP16(so_ + 2*OPB*4, Wl + gw_);                                    \
        }                                                                     \
        CP_COMMIT();                                                          \
    } while (0)

    LOAD_STAGE(0, 0);

    for (int it = 0; it < NK; it++) {
        CP_WAIT0();
        __syncthreads();
        if (it + 1 < NK)
            LOAD_STAGE(it + 1, (it + 1) & 1);

        const uint32_t sb  = smb + (it & 1)*STGU*4;
        const uint32_t ahB = sb;
        const uint32_t whB = sb + OPB*4;
        const uint32_t wlB = sb + 2*OPB*4;

        #pragma unroll
        for (int s16 = 0; s16 < 2; s16++) {
            const uint32_t kbyte = s16 * 32;
            uint32_t ah[2][4];
            #pragma unroll
            for (int mt = 0; mt < 2; mt++) {
                const uint32_t ro = (uint32_t)((wm + mt*16)*RST*4);
                ldsm_x4(ah[mt], ahB + aoff + ro + kbyte);
            }
            #pragma unroll
            for (int ntp = 0; ntp < 4; ntp++) {
                const uint32_t ro = (uint32_t)((wn + ntp*16)*RST*4);
                uint32_t wh4[4], wl4[4];
                ldsm_x4(wh4, whB + boff + ro + kbyte);
                ldsm_x4(wl4, wlB + boff + ro + kbyte);
                #pragma unroll
                for (int j = 0; j < 2; j++) {
                    const int nt = 2*ntp + j;
                    #pragma unroll
                    for (int mt = 0; mt < 2; mt++) {
                        mma_f16(acc[mt][nt], ah[mt], wh4[2*j], wh4[2*j+1]);
                        mma_f16(acc[mt][nt], ah[mt], wl4[2*j], wl4[2*j+1]);
                    }
                }
            }
        }
    }
    #undef LOAD_STAGE
}

// ---------------------------------------------------------------------------
// QKV merged GEMM: grid.z = 0(Q rope), 1(K rope), 2(V transpose-split)
// ---------------------------------------------------------------------------
__global__ __launch_bounds__(256, 2) void gemm_qkv_kernel(
    const __half* __restrict__ Ah,
    const __half* __restrict__ whAll, const __half* __restrict__ wlAll,
    const float* __restrict__ bq, const float* __restrict__ bk,
    const float* __restrict__ bv,
    const float* __restrict__ cosb, const float* __restrict__ sinb,
    __nv_bfloat16* __restrict__ Qhi, __nv_bfloat16* __restrict__ Qlo,
    __nv_bfloat16* __restrict__ Khi, __nv_bfloat16* __restrict__ Klo,
    __nv_bfloat16* __restrict__ Vthi, __nv_bfloat16* __restrict__ Vtlo)
{
    extern __shared__ uint32_t su[];
    const uint32_t smb = (uint32_t)__cvta_generic_to_shared(su);
    const int tid = threadIdx.x;
    const int m0  = blockIdx.y * 128;
    const int n0  = blockIdx.x * 128;
    const int z   = blockIdx.z;

    const __half* Wh = whAll + (size_t)z * NW;
    const __half* Wl = wlAll + (size_t)z * NW;
    const float* bias = (z == 0) ? bq : (z == 1) ? bk : bv;

    float acc[2][8][4];
    #pragma unroll
    for (int mt = 0; mt < 2; mt++)
        #pragma unroll
        for (int nt = 0; nt < 8; nt++)
            #pragma unroll
            for (int r = 0; r < 4; r++) acc[mt][nt][r] = 0.f;

    gemm_mainloop(Ah, Wh, Wl, m0, n0, smb, tid, acc);

    const int lane = tid & 31;
    const int w    = tid >> 5;
    const int g    = lane >> 2;
    const int q    = lane & 3;
    const int wm   = (w & 3) * 32;
    const int wn   = (w >> 2) * 64;

    if (z < 2) {
        __nv_bfloat16* ChiT = (z == 0) ? Qhi : Khi;
        __nv_bfloat16* CloT = (z == 0) ? Qlo : Klo;
        uint32_t* HI = (uint32_t*)ChiT;
        uint32_t* LO = (uint32_t*)CloT;
        #pragma unroll
        for (int mt = 0; mt < 2; mt++) {
            const int row0 = m0 + wm + mt*16 + g;
            #pragma unroll
            for (int nt = 0; nt < 4; nt++) {
                const int col = n0 + wn + nt*8 + 2*q;
                const int d = col & 63, h = col >> 6;
                const float bi10 = bias[col],    bi11 = bias[col+1];
                const float bi20 = bias[col+32], bi21 = bias[col+33];
                #pragma unroll
                for (int r2 = 0; r2 < 2; r2++) {
                    const int row = row0 + r2*8;
                    const int b_ = row >> 11, s_ = row & 2047;
                    const float2 cs1 = *(const float2*)&cosb[s_*HD + d];
                    const float2 sn1 = *(const float2*)&sinb[s_*HD + d];
                    const float2 cs2 = *(const float2*)&cosb[s_*HD + d + 32];
                    const float2 sn2 = *(const float2*)&sinb[s_*HD + d + 32];
                    const float x10 = acc[mt][nt  ][r2*2+0] + bi10;
                    const float x11 = acc[mt][nt  ][r2*2+1] + bi11;
                    const float x20 = acc[mt][nt+4][r2*2+0] + bi20;
                    const float x21 = acc[mt][nt+4][r2*2+1] + bi21;
                    const float o10 = x10*cs1.x - x20*sn1.x;
                    const float o11 = x11*cs1.y - x21*sn1.y;
                    const float o20 = x20*cs2.x + x10*sn2.x;
                    const float o21 = x21*cs2.y + x11*sn2.y;
                    const size_t base = (((size_t)b_*HH + h)*SS + s_)*HD;
                    HI[(base + d     ) >> 1] = pack_bf2(o10, o11);
                    LO[(base + d     ) >> 1] = pack_bf2(bf_res(o10), bf_res(o11));
                    HI[(base + d + 32) >> 1] = pack_bf2(o20, o21);
                    LO[(base + d + 32) >> 1] = pack_bf2(bf_res(o20), bf_res(o21));
                }
            }
        }
    } else {
        // V: direct transposed split write [B,H,HD,S]
        #pragma unroll
        for (int mt = 0; mt < 2; mt++) {
            const int row0 = m0 + wm + mt*16 + g;
            #pragma unroll
            for (int nt = 0; nt < 8; nt++) {
                const int col = n0 + wn + nt*8 + 2*q;
                const int h = col >> 6, d = col & 63;
                const float b0 = bias[col], b1 = bias[col+1];
                #pragma unroll
                for (int r2 = 0; r2 < 2; r2++) {
                    const int row = row0 + r2*8;
                    const int b_ = row >> 11, s_ = row & 2047;
                    const float v0 = acc[mt][nt][r2*2+0] + b0;
                    const float v1 = acc[mt][nt][r2*2+1] + b1;
                    const size_t base0 = (((size_t)b_*HH + h)*HD + d)*SS + s_;
                    Vthi[base0]      = __float2bfloat16(v0);
                    Vtlo[base0]      = __float2bfloat16(bf_res(v0));
                    Vthi[base0 + SS] = __float2bfloat16(v1);
                    Vtlo[base0 + SS] = __float2bfloat16(bf_res(v1));
                }
            }
        }
    }
}

// ---------------------------------------------------------------------------
// Output-projection GEMM: A fp16 single (attention out), fp32 out [M,N]
// ---------------------------------------------------------------------------
__global__ __launch_bounds__(256, 2) void gemm_out_kernel(
    const __half* __restrict__ Ah,
    const __half* __restrict__ Wh, const __half* __restrict__ Wl,
    const float* __restrict__ bias, float* __restrict__ Cf)
{
    extern __shared__ uint32_t su[];
    const uint32_t smb = (uint32_t)__cvta_generic_to_shared(su);
    const int tid = threadIdx.x;
    const int m0  = blockIdx.y * 128;
    const int n0  = blockIdx.x * 128;

    float acc[2][8][4];
    #pragma unroll
    for (int mt = 0; mt < 2; mt++)
        #pragma unroll
        for (int nt = 0; nt < 8; nt++)
            #pragma unroll
            for (int r = 0; r < 4; r++) acc[mt][nt][r] = 0.f;

    gemm_mainloop(Ah, Wh, Wl, m0, n0, smb, tid, acc);

    const int lane = tid & 31;
    const int w    = tid >> 5;
    const int g    = lane >> 2;
    const int q    = lane & 3;
    const int wm   = (w & 3) * 32;
    const int wn   = (w >> 2) * 64;

    #pragma unroll
    for (int mt = 0; mt < 2; mt++) {
        const int row0 = m0 + wm + mt*16 + g;
        const int row1 = row0 + 8;
        #pragma unroll
        for (int nt = 0; nt < 8; nt++) {
            const int col = n0 + wn + nt*8 + 2*q;
            const float b0 = bias[col], b1 = bias[col + 1];
            *(float2*)&Cf[(size_t)row0*DD + col] =
                make_float2(acc[mt][nt][0] + b0, acc[mt][nt][1] + b1);
            *(float2*)&Cf[(size_t)row1*DD + col] =
                make_float2(acc[mt][nt][2] + b0, acc[mt][nt][3] + b1);
        }
    }
}

// ---------------------------------------------------------------------------
// FlashAttention-2 (causal), bf16x3 — exact R12 kernel; epilogue now emits
// fp16 single (feeds the fp16 out-projection).
// ---------------------------------------------------------------------------
#define KST 36
#define ATILE (64*KST)
#define ASTG  (4*ATILE)
#define ATTN_SMEM (2*ASTG*4)

__device__ __forceinline__ void attn_prefetch(
    uint32_t sstage,
    const __nv_bfloat16* __restrict__ Kh, const __nv_bfloat16* __restrict__ Kl,
    const __nv_bfloat16* __restrict__ Vth, const __nv_bfloat16* __restrict__ Vtl,
    size_t hb, int bh, int k0, int tid)
{
    #pragma unroll
    for (int i = 0; i < 4; i++) {
        int c = tid + 128*i;
        int row = c >> 3, c16 = c & 7;
        uint32_t so = sstage + (uint32_t)((row*KST + c16*4)*4);
        size_t ko = hb + (size_t)(k0 + row)*HD + c16*8;
        CP16(so,             Kh + ko);
        CP16(so + ATILE*4,   Kl + ko);
        size_t vo = ((size_t)bh*HD + row)*SS + k0 + c16*8;
        CP16(so + 2*ATILE*4, Vth + vo);
        CP16(so + 3*ATILE*4, Vtl + vo);
    }
    CP_COMMIT();
}

__global__ __launch_bounds__(128) void attn_bf3_kernel(
    const __nv_bfloat16* __restrict__ Qh, const __nv_bfloat16* __restrict__ Ql,
    const __nv_bfloat16* __restrict__ Kh, const __nv_bfloat16* __restrict__ Kl,
    const __nv_bfloat16* __restrict__ Vth, const __nv_bfloat16* __restrict__ Vtl,
    __half* __restrict__ OutH)
{
    extern __shared__ uint32_t su[];
    const uint32_t smb = (uint32_t)__cvta_generic_to_shared(su);

    const int tid  = threadIdx.x;
    const int w    = tid >> 5;
    const int lane = tid & 31;
    const int g    = lane >> 2;
    const int q    = lane & 3;
    const int qt   = (SS/64 - 1) - blockIdx.x;
    const int bh   = blockIdx.y;
    const int q0   = qt * 64;
    const size_t hb = (size_t)bh * SS * HD;

    const uint32_t aoff = (uint32_t)(((((lane>>3)&1)*8 + (lane&7))*KST + ((lane>>4)*4)) * 4);
    const uint32_t boff = (uint32_t)((((lane>>4)*8 + (lane&7))*KST + (((lane>>3)&1)*4)) * 4);

    #pragma unroll
    for (int i = 0; i < 4; i++) {
        int c = tid + 128*i;
        int row = c >> 3, c16 = c & 7;
        uint32_t so = smb + ASTG*4 + (uint32_t)((row*KST + c16*4)*4);
        size_t go = hb + (size_t)(q0 + row)*HD + c16*8;
        CP16(so,           Qh + go);
        CP16(so + ATILE*4, Ql + go);
    }
    CP_COMMIT();
    attn_prefetch(smb, Kh, Kl, Vth, Vtl, hb, bh, 0, tid);

    CP_WAIT1();
    __syncthreads();

    const int rb = 16*w;
    uint32_t rQh[4][4], rQl[4][4];
    #pragma unroll
    for (int ks = 0; ks < 4; ks++) {
        const uint32_t ro = (uint32_t)(rb*KST*4) + ks*32;
        ldsm_x4(rQh[ks], smb + ASTG*4 + aoff + ro);
        ldsm_x4(rQl[ks], smb + ASTG*4 + ATILE*4 + aoff + ro);
    }
    __syncthreads();
    if (qt > 0)
        attn_prefetch(smb + ASTG*4, Kh, Kl, Vth, Vtl, hb, bh, 64, tid);

    float oc[8][4];
    #pragma unroll
    for (int nt = 0; nt < 8; nt++)
        #pragma unroll
        for (int r = 0; r < 4; r++) oc[nt][r] = 0.f;
    float m0 = -1e30f, m1 = -1e30f, l0 = 0.f, l1 = 0.f;

    const int row0g = q0 + 16*w + g;
    const int row1g = row0g + 8;

    for (int kt = 0; kt <= qt; kt++) {
        const int k0 = kt * 64;
        const uint32_t ab   = smb + (kt & 1)*ASTG*4;
        const uint32_t aKsH = ab;
        const uint32_t aKsL = ab + ATILE*4;
        const uint32_t aVsH = ab + 2*ATILE*4;
        const uint32_t aVsL = ab + 3*ATILE*4;

        if (kt < qt) { CP_WAIT1(); } else { CP_WAIT0(); }
        __syncthreads();

        float sc[8][4];
        #pragma unroll
        for (int nt = 0; nt < 8; nt++)
            #pragma unroll
            for (int r = 0; r < 4; r++) sc[nt][r] = 0.f;

        #pragma unroll
        for (int ks = 0; ks < 4; ks++) {
            const uint32_t kbyte = ks*32;
            #pragma unroll
            for (int ntp = 0; ntp < 4; ntp++) {
                const uint32_t ro = (uint32_t)(ntp*16*KST*4) + kbyte;
                uint32_t kh4[4], kl4[4];
                ldsm_x4(kh4, aKsH + boff + ro);
                ldsm_x4(kl4, aKsL + boff + ro);
                #pragma unroll
                for (int j = 0; j < 2; j++) {
                    const int nt = 2*ntp + j;
                    mma_bf16(sc[nt], rQh[ks], kh4[2*j], kh4[2*j+1]);
                    mma_bf16(sc[nt], rQh[ks], kl4[2*j], kl4[2*j+1]);
                    mma_bf16(sc[nt], rQl[ks], kh4[2*j], kh4[2*j+1]);
                }
            }
        }

        const float scale2 = 0.18033688f;   // 0.125 * log2(e)
        const bool diag = (kt == qt);
        #pragma unroll
        for (int nt = 0; nt < 8; nt++) {
            const int colb = k0 + nt*8 + 2*q;
            #pragma unroll
            for (int j = 0; j < 2; j++) {
                float v0 = sc[nt][j]   * scale2;
                float v1 = sc[nt][2+j] * scale2;
                if (diag && (colb + j) > row0g) v0 = -1e30f;
                if (diag && (colb + j) > row1g) v1 = -1e30f;
                sc[nt][j]   = v0;
                sc[nt][2+j] = v1;
            }
        }

        float mx0 = -1e30f, mx1 = -1e30f;
        #pragma unroll
        for (int nt = 0; nt < 8; nt++) {
            mx0 = fmaxf(mx0, fmaxf(sc[nt][0], sc[nt][1]));
            mx1 = fmaxf(mx1, fmaxf(sc[nt][2], sc[nt][3]));
        }
        mx0 = fmaxf(mx0, __shfl_xor_sync(0xffffffffu, mx0, 1));
        mx0 = fmaxf(mx0, __shfl_xor_sync(0xffffffffu, mx0, 2));
        mx1 = fmaxf(mx1, __shfl_xor_sync(0xffffffffu, mx1, 1));
        mx1 = fmaxf(mx1, __shfl_xor_sync(0xffffffffu, mx1, 2));
        const float mn0 = fmaxf(m0, mx0);
        const float mn1 = fmaxf(m1, mx1);
        const float a0 = exp2f(m0 - mn0);
        const float a1 = exp2f(m1 - mn1);
        m0 = mn0; m1 = mn1;

        uint32_t ph[8][2], pl[8][2];
        float s0 = 0.f, s1 = 0.f;
        #pragma unroll
        for (int nt = 0; nt < 8; nt++) {
            float p00 = exp2f(sc[nt][0] - mn0);
            float p01 = exp2f(sc[nt][1] - mn0);
            float p10 = exp2f(sc[nt][2] - mn1);
            float p11 = exp2f(sc[nt][3] - mn1);
            s0 += p00 + p01;
            s1 += p10 + p11;
            ph[nt][0] = pack_bf2(p00, p01);
            ph[nt][1] = pack_bf2(p10, p11);
            pl[nt][0] = pack_bf2(bf_res(p00), bf_res(p01));
            pl[nt][1] = pack_bf2(bf_res(p10), bf_res(p11));
        }
        s0 += __shfl_xor_sync(0xffffffffu, s0, 1);
        s0 += __shfl_xor_sync(0xffffffffu, s0, 2);
        s1 += __shfl_xor_sync(0xffffffffu, s1, 1);
        s1 += __shfl_xor_sync(0xffffffffu, s1, 2);
        l0 = l0*a0 + s0;
        l1 = l1*a1 + s1;
        #pragma unroll
        for (int nt = 0; nt < 8; nt++) {
            oc[nt][0] *= a0; oc[nt][1] *= a0;
            oc[nt][2] *= a1; oc[nt][3] *= a1;
        }

        #pragma unroll
        for (int kc = 0; kc < 4; kc++) {
            uint32_t ah4[4] = { ph[2*kc][0], ph[2*kc][1], ph[2*kc+1][0], ph[2*kc+1][1] };
            uint32_t al4[4] = { pl[2*kc][0], pl[2*kc][1], pl[2*kc+1][0], pl[2*kc+1][1] };
            const uint32_t kbyte = kc*32;
            #pragma unroll
            for (int ntp = 0; ntp < 4; ntp++) {
                const uint32_t ro = (uint32_t)(ntp*16*KST*4) + kbyte;
                uint32_t vh4[4], vl4[4];
                ldsm_x4(vh4, aVsH + boff + ro);
                ldsm_x4(vl4, aVsL + boff + ro);
                #pragma unroll
                for (int j = 0; j < 2; j++) {
                    const int nto = 2*ntp + j;
                    mma_bf16(oc[nto], ah4, vh4[2*j], vh4[2*j+1]);
                    mma_bf16(oc[nto], ah4, vl4[2*j], vl4[2*j+1]);
                    mma_bf16(oc[nto], al4, vh4[2*j], vh4[2*j+1]);
                }
            }
        }

        __syncthreads();
        if (kt + 2 <= qt)
            attn_prefetch(ab, Kh, Kl, Vth, Vtl, hb, bh, (kt + 2)*64, tid);
    }

    // epilogue: normalize + write fp16 single [B,S,D]
    const float i0 = 1.f / l0;
    const float i1 = 1.f / l1;
    const int b = bh >> 4;
    const int h = bh & 15;
    const size_t o0 = ((size_t)(b*SS + row0g))*DD + h*HD;
    const size_t o1 = ((size_t)(b*SS + row1g))*DD + h*HD;
    uint32_t* HO = (uint32_t*)OutH;
    #pragma unroll
    for (int nt = 0; nt < 8; nt++) {
        const int col = nt*8 + 2*q;
        HO[(o0 + col) >> 1] = pack_h2(oc[nt][0]*i0, oc[nt][1]*i0);
        HO[(o1 + col) >> 1] = pack_h2(oc[nt][2]*i1, oc[nt][3]*i1);
    }
}

// ---------------------------------------------------------------------------
// Launch
// ---------------------------------------------------------------------------
extern "C" void kernel_launch(void* const* d_in, const int* in_sizes, int n_in,
                              void* d_out, int out_size)
{
    const float* x    = (const float*)d_in[0];
    const float* cosb = (const float*)d_in[1];
    const float* sinb = (const float*)d_in[2];
    const float* Wq = (const float*)d_in[4];
    const float* bq = (const float*)d_in[5];
    const float* Wk = (const float*)d_in[6];
    const float* bk = (const float*)d_in[7];
    const float* Wv = (const float*)d_in[8];
    const float* bv = (const float*)d_in[9];
    const float* Wo = (const float*)d_in[10];
    const float* bo = (const float*)d_in[11];
    float* out = (float*)d_out;

    __half *xh, *ah, *wh, *wl;
    __nv_bfloat16 *qhi, *qlo, *khi, *klo, *vthi, *vtlo;
    cudaGetSymbolAddress((void**)&xh,   g_xh);
    cudaGetSymbolAddress((void**)&ah,   g_ah);
    cudaGetSymbolAddress((void**)&wh,   g_wh);
    cudaGetSymbolAddress((void**)&wl,   g_wl);
    cudaGetSymbolAddress((void**)&qhi,  g_qhi);
    cudaGetSymbolAddress((void**)&qlo,  g_qlo);
    cudaGetSymbolAddress((void**)&khi,  g_khi);
    cudaGetSymbolAddress((void**)&klo,  g_klo);
    cudaGetSymbolAddress((void**)&vthi, g_vthi);
    cudaGetSymbolAddress((void**)&vtlo, g_vtlo);

    cudaFuncSetAttribute(gemm_qkv_kernel,
                         cudaFuncAttributeMaxDynamicSharedMemorySize, GEMM_SMEM);
    cudaFuncSetAttribute(gemm_out_kernel,
                         cudaFuncAttributeMaxDynamicSharedMemorySize, GEMM_SMEM);
    cudaFuncSetAttribute(attn_bf3_kernel,
                         cudaFuncAttributeMaxDynamicSharedMemorySize, ATTN_SMEM);

    split_all_kernel<<<SPLIT_BLOCKS, 256>>>(x, Wq, Wk, Wv, Wo, xh, wh, wl);
    gemm_qkv_kernel<<<dim3(DD/128, BS/128, 3), 256, GEMM_SMEM>>>(
        xh, wh, wl, bq, bk, bv, cosb, sinb,
        qhi, qlo, khi, klo, vthi, vtlo);
    attn_bf3_kernel<<<dim3(SS/64, BB*HH), 128, ATTN_SMEM>>>(
        qhi, qlo, khi, klo, vthi, vtlo, ah);
    gemm_out_kernel<<<dim3(DD/128, BS/128), 256, GEMM_SMEM>>>(
        ah, wh + 3*(size_t)NW, wl + 3*(size_t)NW, bo, out);
}

// round 15
// speedup vs baseline: 1.4092x; 1.0846x over previous
#include <cuda_runtime.h>
#include <cuda_bf16.h>
#include <cuda_fp16.h>
#include <stdint.h>

// Problem constants
#define BB 4
#define SS 2048
#define DD 1024
#define HH 16
#define HD 64
#define BS (BB*SS)
#define NQ (BB*HH*SS*HD)
#define NX (BS*DD)
#define NW (DD*DD)

// ---------------------------------------------------------------------------
// Static device scratch
// ---------------------------------------------------------------------------
__device__ __half g_xh[NX];                           // x fp16 single
__device__ __half g_ah[NX];                           // attention out fp16 single
__device__ __half g_wh[4][NW], g_wl[4][NW];           // weights fp16 hi/lo
__device__ __half g_qh[NQ];                           // Q fp16 single [B,H,S,HD]
__device__ __half g_kh2[NQ], g_kl2[NQ];               // K fp16 hi/lo [B,H,S,HD]
__device__ __half g_vth2[NQ], g_vtl2[NQ];             // V fp16 hi/lo [B,H,HD,S]

// ---------------------------------------------------------------------------
// helpers
// ---------------------------------------------------------------------------
__device__ __forceinline__ uint32_t pack_h2(float a, float b) {
    __half ha = __float2half_rn(a), hb = __float2half_rn(b);
    unsigned short ua = *reinterpret_cast<unsigned short*>(&ha);
    unsigned short ub = *reinterpret_cast<unsigned short*>(&hb);
    return (uint32_t)ua | ((uint32_t)ub << 16);
}
__device__ __forceinline__ float h_res(float x) {
    return x - __half2float(__float2half_rn(x));
}

__device__ __forceinline__ void mma_f16(float* c, const uint32_t* a,
                                        uint32_t b0, uint32_t b1)
{
    asm("mma.sync.aligned.m16n8k16.row.col.f32.f16.f16.f32 "
        "{%0,%1,%2,%3},{%4,%5,%6,%7},{%8,%9},{%0,%1,%2,%3};"
        : "+f"(c[0]), "+f"(c[1]), "+f"(c[2]), "+f"(c[3])
        : "r"(a[0]), "r"(a[1]), "r"(a[2]), "r"(a[3]), "r"(b0), "r"(b1));
}

__device__ __forceinline__ void ldsm_x4(uint32_t* r, uint32_t addr) {
    asm volatile("ldmatrix.sync.aligned.m8n8.x4.shared.b16 {%0,%1,%2,%3}, [%4];"
        : "=r"(r[0]), "=r"(r[1]), "=r"(r[2]), "=r"(r[3]) : "r"(addr));
}

#define CP16(dst_smem_u32, src_gptr) \
    asm volatile("cp.async.cg.shared.global [%0], [%1], 16;\n" \
                 :: "r"(dst_smem_u32), "l"(src_gptr))
#define CP_COMMIT() asm volatile("cp.async.commit_group;\n")
#define CP_WAIT1()  asm volatile("cp.async.wait_group 1;\n")
#define CP_WAIT0()  asm volatile("cp.async.wait_group 0;\n")

// ---------------------------------------------------------------------------
// merged split: x -> fp16 single; 4 weights -> fp16 hi/lo
// ---------------------------------------------------------------------------
__global__ __launch_bounds__(256) void split_all_kernel(
    const float* __restrict__ x,
    const float* __restrict__ W0, const float* __restrict__ W1,
    const float* __restrict__ W2, const float* __restrict__ W3,
    __half* __restrict__ xh, __half* __restrict__ wh, __half* __restrict__ wl)
{
    const int gi = blockIdx.x * 256 + threadIdx.x;   // < NX/4 + NW
    if (gi < NX/4) {
        float4 v = ((const float4*)x)[gi];
        ((uint2*)xh)[gi] = make_uint2(pack_h2(v.x, v.y), pack_h2(v.z, v.w));
    } else {
        const int wi = gi - NX/4;
        const int z  = wi >> 18;             // / (NW/4 = 262144)
        const int j  = wi & 262143;
        const float* src = (z == 0) ? W0 : (z == 1) ? W1 : (z == 2) ? W2 : W3;
        float4 v = ((const float4*)src)[j];
        const size_t o = (size_t)z * (NW/4) + j;
        ((uint2*)wh)[o] = make_uint2(pack_h2(v.x, v.y), pack_h2(v.z, v.w));
        ((uint2*)wl)[o] = make_uint2(pack_h2(h_res(v.x), h_res(v.y)),
                                     pack_h2(h_res(v.z), h_res(v.w)));
    }
}
#define SPLIT_BLOCKS ((NX/4 + NW) / 256)     // 12288

// ---------------------------------------------------------------------------
// fp16x2 GEMM mainloop (R14 proven): A single x W hi/lo, 2 MMAs per k16.
// ---------------------------------------------------------------------------
#define RST 20
#define OPB (128*RST)
#define STGU (3*OPB)
#define GEMM_SMEM (2*STGU*4)     // 61440 B

__device__ __forceinline__ void gemm_mainloop(
    const __half* __restrict__ Ah,
    const __half* __restrict__ Wh, const __half* __restrict__ Wl,
    int m0, int n0, uint32_t smb, int tid, float acc[2][8][4])
{
    const int lane = tid & 31;
    const int w    = tid >> 5;
    const int wm   = (w & 3) * 32;
    const int wn   = (w >> 2) * 64;
    const uint32_t aoff = (uint32_t)(((((lane>>3)&1)*8 + (lane&7))*RST + ((lane>>4)*4)) * 4);
    const uint32_t boff = (uint32_t)((((lane>>4)*8 + (lane&7))*RST + (((lane>>3)&1)*4)) * 4);

    const int NK = DD / 32;

    #define LOAD_STAGE(kt, stg) do {                                          \
        uint32_t sb_ = smb + (stg)*STGU*4;                                    \
        _Pragma("unroll")                                                     \
        for (int i_ = 0; i_ < 2; i_++) {                                      \
            int c_ = tid + 256*i_;                                            \
            int row_ = c_ >> 2, c16_ = c_ & 3;                                \
            uint32_t so_ = sb_ + (uint32_t)((row_*RST + c16_*4)*4);           \
            size_t ga_ = (size_t)(m0+row_)*DD + (kt)*32 + c16_*8;             \
            size_t gw_ = (size_t)(n0+row_)*DD + (kt)*32 + c16_*8;             \
            CP16(so_,           Ah + ga_);                                    \
            CP16(so_ + OPB*4,   Wh + gw_);                                    \
            CP16(so_ + 2*OPB*4, Wl + gw_);                                    \
        }                                                                     \
        CP_COMMIT();                                                          \
    } while (0)

    LOAD_STAGE(0, 0);

    for (int it = 0; it < NK; it++) {
        CP_WAIT0();
        __syncthreads();
        if (it + 1 < NK)
            LOAD_STAGE(it + 1, (it + 1) & 1);

        const uint32_t sb  = smb + (it & 1)*STGU*4;
        const uint32_t ahB = sb;
        const uint32_t whB = sb + OPB*4;
        const uint32_t wlB = sb + 2*OPB*4;

        #pragma unroll
        for (int s16 = 0; s16 < 2; s16++) {
            const uint32_t kbyte = s16 * 32;
            uint32_t ah[2][4];
            #pragma unroll
            for (int mt = 0; mt < 2; mt++) {
                const uint32_t ro = (uint32_t)((wm + mt*16)*RST*4);
                ldsm_x4(ah[mt], ahB + aoff + ro + kbyte);
            }
            #pragma unroll
            for (int ntp = 0; ntp < 4; ntp++) {
                const uint32_t ro = (uint32_t)((wn + ntp*16)*RST*4);
                uint32_t wh4[4], wl4[4];
                ldsm_x4(wh4, whB + boff + ro + kbyte);
                ldsm_x4(wl4, wlB + boff + ro + kbyte);
                #pragma unroll
                for (int j = 0; j < 2; j++) {
                    const int nt = 2*ntp + j;
                    #pragma unroll
                    for (int mt = 0; mt < 2; mt++) {
                        mma_f16(acc[mt][nt], ah[mt], wh4[2*j], wh4[2*j+1]);
                        mma_f16(acc[mt][nt], ah[mt], wl4[2*j], wl4[2*j+1]);
                    }
                }
            }
        }
    }
    #undef LOAD_STAGE
}

// ---------------------------------------------------------------------------
// QKV merged GEMM: z=0: Q rope -> fp16 single; z=1: K rope -> fp16 hi/lo;
// z=2: V transpose -> fp16 hi/lo
// ---------------------------------------------------------------------------
__global__ __launch_bounds__(256, 2) void gemm_qkv_kernel(
    const __half* __restrict__ Ah,
    const __half* __restrict__ whAll, const __half* __restrict__ wlAll,
    const float* __restrict__ bq, const float* __restrict__ bk,
    const float* __restrict__ bv,
    const float* __restrict__ cosb, const float* __restrict__ sinb,
    __half* __restrict__ Qh,
    __half* __restrict__ Khi, __half* __restrict__ Klo,
    __half* __restrict__ Vthi, __half* __restrict__ Vtlo)
{
    extern __shared__ uint32_t su[];
    const uint32_t smb = (uint32_t)__cvta_generic_to_shared(su);
    const int tid = threadIdx.x;
    const int m0  = blockIdx.y * 128;
    const int n0  = blockIdx.x * 128;
    const int z   = blockIdx.z;

    const __half* Wh = whAll + (size_t)z * NW;
    const __half* Wl = wlAll + (size_t)z * NW;
    const float* bias = (z == 0) ? bq : (z == 1) ? bk : bv;

    float acc[2][8][4];
    #pragma unroll
    for (int mt = 0; mt < 2; mt++)
        #pragma unroll
        for (int nt = 0; nt < 8; nt++)
            #pragma unroll
            for (int r = 0; r < 4; r++) acc[mt][nt][r] = 0.f;

    gemm_mainloop(Ah, Wh, Wl, m0, n0, smb, tid, acc);

    const int lane = tid & 31;
    const int w    = tid >> 5;
    const int g    = lane >> 2;
    const int q    = lane & 3;
    const int wm   = (w & 3) * 32;
    const int wn   = (w >> 2) * 64;

    if (z < 2) {
        uint32_t* HI = (z == 0) ? (uint32_t*)Qh  : (uint32_t*)Khi;
        uint32_t* LO = (z == 0) ? nullptr        : (uint32_t*)Klo;
        #pragma unroll
        for (int mt = 0; mt < 2; mt++) {
            const int row0 = m0 + wm + mt*16 + g;
            #pragma unroll
            for (int nt = 0; nt < 4; nt++) {
                const int col = n0 + wn + nt*8 + 2*q;
                const int d = col & 63, h = col >> 6;
                const float bi10 = bias[col],    bi11 = bias[col+1];
                const float bi20 = bias[col+32], bi21 = bias[col+33];
                #pragma unroll
                for (int r2 = 0; r2 < 2; r2++) {
                    const int row = row0 + r2*8;
                    const int b_ = row >> 11, s_ = row & 2047;
                    const float2 cs1 = *(const float2*)&cosb[s_*HD + d];
                    const float2 sn1 = *(const float2*)&sinb[s_*HD + d];
                    const float2 cs2 = *(const float2*)&cosb[s_*HD + d + 32];
                    const float2 sn2 = *(const float2*)&sinb[s_*HD + d + 32];
                    const float x10 = acc[mt][nt  ][r2*2+0] + bi10;
                    const float x11 = acc[mt][nt  ][r2*2+1] + bi11;
                    const float x20 = acc[mt][nt+4][r2*2+0] + bi20;
                    const float x21 = acc[mt][nt+4][r2*2+1] + bi21;
                    const float o10 = x10*cs1.x - x20*sn1.x;
                    const float o11 = x11*cs1.y - x21*sn1.y;
                    const float o20 = x20*cs2.x + x10*sn2.x;
                    const float o21 = x21*cs2.y + x11*sn2.y;
                    const size_t base = (((size_t)b_*HH + h)*SS + s_)*HD;
                    HI[(base + d     ) >> 1] = pack_h2(o10, o11);
                    HI[(base + d + 32) >> 1] = pack_h2(o20, o21);
                    if (z == 1) {
                        LO[(base + d     ) >> 1] = pack_h2(h_res(o10), h_res(o11));
                        LO[(base + d + 32) >> 1] = pack_h2(h_res(o20), h_res(o21));
                    }
                }
            }
        }
    } else {
        // V: direct transposed fp16 hi/lo write [B,H,HD,S]
        #pragma unroll
        for (int mt = 0; mt < 2; mt++) {
            const int row0 = m0 + wm + mt*16 + g;
            #pragma unroll
            for (int nt = 0; nt < 8; nt++) {
                const int col = n0 + wn + nt*8 + 2*q;
                const int h = col >> 6, d = col & 63;
                const float b0 = bias[col], b1 = bias[col+1];
                #pragma unroll
                for (int r2 = 0; r2 < 2; r2++) {
                    const int row = row0 + r2*8;
                    const int b_ = row >> 11, s_ = row & 2047;
                    const float v0 = acc[mt][nt][r2*2+0] + b0;
                    const float v1 = acc[mt][nt][r2*2+1] + b1;
                    const size_t base0 = (((size_t)b_*HH + h)*HD + d)*SS + s_;
                    Vthi[base0]      = __float2half_rn(v0);
                    Vtlo[base0]      = __float2half_rn(h_res(v0));
                    Vthi[base0 + SS] = __float2half_rn(v1);
                    Vtlo[base0 + SS] = __float2half_rn(h_res(v1));
                }
            }
        }
    }
}

// ---------------------------------------------------------------------------
// Output-projection GEMM: fp32 out [M,N]
// ---------------------------------------------------------------------------
__global__ __launch_bounds__(256, 2) void gemm_out_kernel(
    const __half* __restrict__ Ah,
    const __half* __restrict__ Wh, const __half* __restrict__ Wl,
    const float* __restrict__ bias, float* __restrict__ Cf)
{
    extern __shared__ uint32_t su[];
    const uint32_t smb = (uint32_t)__cvta_generic_to_shared(su);
    const int tid = threadIdx.x;
    const int m0  = blockIdx.y * 128;
    const int n0  = blockIdx.x * 128;

    float acc[2][8][4];
    #pragma unroll
    for (int mt = 0; mt < 2; mt++)
        #pragma unroll
        for (int nt = 0; nt < 8; nt++)
            #pragma unroll
            for (int r = 0; r < 4; r++) acc[mt][nt][r] = 0.f;

    gemm_mainloop(Ah, Wh, Wl, m0, n0, smb, tid, acc);

    const int lane = tid & 31;
    const int w    = tid >> 5;
    const int g    = lane >> 2;
    const int q    = lane & 3;
    const int wm   = (w & 3) * 32;
    const int wn   = (w >> 2) * 64;

    #pragma unroll
    for (int mt = 0; mt < 2; mt++) {
        const int row0 = m0 + wm + mt*16 + g;
        const int row1 = row0 + 8;
        #pragma unroll
        for (int nt = 0; nt < 8; nt++) {
            const int col = n0 + wn + nt*8 + 2*q;
            const float b0 = bias[col], b1 = bias[col + 1];
            *(float2*)&Cf[(size_t)row0*DD + col] =
                make_float2(acc[mt][nt][0] + b0, acc[mt][nt][1] + b1);
            *(float2*)&Cf[(size_t)row1*DD + col] =
                make_float2(acc[mt][nt][2] + b0, acc[mt][nt][3] + b1);
        }
    }
}

// ---------------------------------------------------------------------------
// FlashAttention-2 (causal), fp16x2: scores = Q(single) x K(hi/lo),
// PV = P(single) x V(hi/lo). 128 threads, 64-row q-tiles, cp.async dbuf.
// ---------------------------------------------------------------------------
#define KST 36
#define ATILE (64*KST)
#define ASTG  (4*ATILE)          // {Kh, Kl, Vh, Vl}
#define ATTN_SMEM (2*ASTG*4)

__device__ __forceinline__ void attn_prefetch(
    uint32_t sstage,
    const __half* __restrict__ Kh, const __half* __restrict__ Kl,
    const __half* __restrict__ Vth, const __half* __restrict__ Vtl,
    size_t hb, int bh, int k0, int tid)
{
    #pragma unroll
    for (int i = 0; i < 4; i++) {
        int c = tid + 128*i;
        int row = c >> 3, c16 = c & 7;
        uint32_t so = sstage + (uint32_t)((row*KST + c16*4)*4);
        size_t ko = hb + (size_t)(k0 + row)*HD + c16*8;
        CP16(so,             Kh + ko);
        CP16(so + ATILE*4,   Kl + ko);
        size_t vo = ((size_t)bh*HD + row)*SS + k0 + c16*8;
        CP16(so + 2*ATILE*4, Vth + vo);
        CP16(so + 3*ATILE*4, Vtl + vo);
    }
    CP_COMMIT();
}

__global__ __launch_bounds__(128) void attn_f16_kernel(
    const __half* __restrict__ Qh,
    const __half* __restrict__ Kh, const __half* __restrict__ Kl,
    const __half* __restrict__ Vth, const __half* __restrict__ Vtl,
    __half* __restrict__ OutH)
{
    extern __shared__ uint32_t su[];
    const uint32_t smb = (uint32_t)__cvta_generic_to_shared(su);

    const int tid  = threadIdx.x;
    const int w    = tid >> 5;
    const int lane = tid & 31;
    const int g    = lane >> 2;
    const int q    = lane & 3;
    const int qt   = (SS/64 - 1) - blockIdx.x;
    const int bh   = blockIdx.y;
    const int q0   = qt * 64;
    const size_t hb = (size_t)bh * SS * HD;

    const uint32_t aoff = (uint32_t)(((((lane>>3)&1)*8 + (lane&7))*KST + ((lane>>4)*4)) * 4);
    const uint32_t boff = (uint32_t)((((lane>>4)*8 + (lane&7))*KST + (((lane>>3)&1)*4)) * 4);

    // stage Q (single) into stage1's Kh area via cp.async
    #pragma unroll
    for (int i = 0; i < 4; i++) {
        int c = tid + 128*i;
        int row = c >> 3, c16 = c & 7;
        uint32_t so = smb + ASTG*4 + (uint32_t)((row*KST + c16*4)*4);
        size_t go = hb + (size_t)(q0 + row)*HD + c16*8;
        CP16(so, Qh + go);
    }
    CP_COMMIT();
    attn_prefetch(smb, Kh, Kl, Vth, Vtl, hb, bh, 0, tid);

    CP_WAIT1();
    __syncthreads();

    const int rb = 16*w;
    uint32_t rQ[4][4];
    #pragma unroll
    for (int ks = 0; ks < 4; ks++) {
        const uint32_t ro = (uint32_t)(rb*KST*4) + ks*32;
        ldsm_x4(rQ[ks], smb + ASTG*4 + aoff + ro);
    }
    __syncthreads();
    if (qt > 0)
        attn_prefetch(smb + ASTG*4, Kh, Kl, Vth, Vtl, hb, bh, 64, tid);

    float oc[8][4];
    #pragma unroll
    for (int nt = 0; nt < 8; nt++)
        #pragma unroll
        for (int r = 0; r < 4; r++) oc[nt][r] = 0.f;
    float m0 = -1e30f, m1 = -1e30f, l0 = 0.f, l1 = 0.f;

    const int row0g = q0 + 16*w + g;
    const int row1g = row0g + 8;

    for (int kt = 0; kt <= qt; kt++) {
        const int k0 = kt * 64;
        const uint32_t ab   = smb + (kt & 1)*ASTG*4;
        const uint32_t aKsH = ab;
        const uint32_t aKsL = ab + ATILE*4;
        const uint32_t aVsH = ab + 2*ATILE*4;
        const uint32_t aVsL = ab + 3*ATILE*4;

        if (kt < qt) { CP_WAIT1(); } else { CP_WAIT0(); }
        __syncthreads();

        float sc[8][4];
        #pragma unroll
        for (int nt = 0; nt < 8; nt++)
            #pragma unroll
            for (int r = 0; r < 4; r++) sc[nt][r] = 0.f;

        // scores: Q(single) x K(hi/lo) -> 2 MMAs per (ks, acc)
        #pragma unroll
        for (int ks = 0; ks < 4; ks++) {
            const uint32_t kbyte = ks*32;
            #pragma unroll
            for (int ntp = 0; ntp < 4; ntp++) {
                const uint32_t ro = (uint32_t)(ntp*16*KST*4) + kbyte;
                uint32_t kh4[4], kl4[4];
                ldsm_x4(kh4, aKsH + boff + ro);
                ldsm_x4(kl4, aKsL + boff + ro);
                #pragma unroll
                for (int j = 0; j < 2; j++) {
                    const int nt = 2*ntp + j;
                    mma_f16(sc[nt], rQ[ks], kh4[2*j], kh4[2*j+1]);
                    mma_f16(sc[nt], rQ[ks], kl4[2*j], kl4[2*j+1]);
                }
            }
        }

        const float scale2 = 0.18033688f;   // 0.125 * log2(e)
        const bool diag = (kt == qt);
        #pragma unroll
        for (int nt = 0; nt < 8; nt++) {
            const int colb = k0 + nt*8 + 2*q;
            #pragma unroll
            for (int j = 0; j < 2; j++) {
                float v0 = sc[nt][j]   * scale2;
                float v1 = sc[nt][2+j] * scale2;
                if (diag && (colb + j) > row0g) v0 = -1e30f;
                if (diag && (colb + j) > row1g) v1 = -1e30f;
                sc[nt][j]   = v0;
                sc[nt][2+j] = v1;
            }
        }

        float mx0 = -1e30f, mx1 = -1e30f;
        #pragma unroll
        for (int nt = 0; nt < 8; nt++) {
            mx0 = fmaxf(mx0, fmaxf(sc[nt][0], sc[nt][1]));
            mx1 = fmaxf(mx1, fmaxf(sc[nt][2], sc[nt][3]));
        }
        mx0 = fmaxf(mx0, __shfl_xor_sync(0xffffffffu, mx0, 1));
        mx0 = fmaxf(mx0, __shfl_xor_sync(0xffffffffu, mx0, 2));
        mx1 = fmaxf(mx1, __shfl_xor_sync(0xffffffffu, mx1, 1));
        mx1 = fmaxf(mx1, __shfl_xor_sync(0xffffffffu, mx1, 2));
        const float mn0 = fmaxf(m0, mx0);
        const float mn1 = fmaxf(m1, mx1);
        const float a0 = exp2f(m0 - mn0);
        const float a1 = exp2f(m1 - mn1);
        m0 = mn0; m1 = mn1;

        uint32_t ph[8][2];
        float s0 = 0.f, s1 = 0.f;
        #pragma unroll
        for (int nt = 0; nt < 8; nt++) {
            float p00 = exp2f(sc[nt][0] - mn0);
            float p01 = exp2f(sc[nt][1] - mn0);
            float p10 = exp2f(sc[nt][2] - mn1);
            float p11 = exp2f(sc[nt][3] - mn1);
            s0 += p00 + p01;
            s1 += p10 + p11;
            ph[nt][0] = pack_h2(p00, p01);
            ph[nt][1] = pack_h2(p10, p11);
        }
        s0 += __shfl_xor_sync(0xffffffffu, s0, 1);
        s0 += __shfl_xor_sync(0xffffffffu, s0, 2);
        s1 += __shfl_xor_sync(0xffffffffu, s1, 1);
        s1 += __shfl_xor_sync(0xffffffffu, s1, 2);
        l0 = l0*a0 + s0;
        l1 = l1*a1 + s1;
        #pragma unroll
        for (int nt = 0; nt < 8; nt++) {
            oc[nt][0] *= a0; oc[nt][1] *= a0;
            oc[nt][2] *= a1; oc[nt][3] *= a1;
        }

        // PV: P(single) x V(hi/lo) -> 2 MMAs per (kc, acc)
        #pragma unroll
        for (int kc = 0; kc < 4; kc++) {
            uint32_t ah4[4] = { ph[2*kc][0], ph[2*kc][1], ph[2*kc+1][0], ph[2*kc+1][1] };
            const uint32_t kbyte = kc*32;
            #pragma unroll
            for (int ntp = 0; ntp < 4; ntp++) {
                const uint32_t ro = (uint32_t)(ntp*16*KST*4) + kbyte;
                uint32_t vh4[4], vl4[4];
                ldsm_x4(vh4, aVsH + boff + ro);
                ldsm_x4(vl4, aVsL + boff + ro);
                #pragma unroll
                for (int j = 0; j < 2; j++) {
                    const int nto = 2*ntp + j;
                    mma_f16(oc[nto], ah4, vh4[2*j], vh4[2*j+1]);
                    mma_f16(oc[nto], ah4, vl4[2*j], vl4[2*j+1]);
                }
            }
        }

        __syncthreads();
        if (kt + 2 <= qt)
            attn_prefetch(ab, Kh, Kl, Vth, Vtl, hb, bh, (kt + 2)*64, tid);
    }

    // epilogue: normalize + write fp16 single [B,S,D]
    const float i0 = 1.f / l0;
    const float i1 = 1.f / l1;
    const int b = bh >> 4;
    const int h = bh & 15;
    const size_t o0 = ((size_t)(b*SS + row0g))*DD + h*HD;
    const size_t o1 = ((size_t)(b*SS + row1g))*DD + h*HD;
    uint32_t* HO = (uint32_t*)OutH;
    #pragma unroll
    for (int nt = 0; nt < 8; nt++) {
        const int col = nt*8 + 2*q;
        HO[(o0 + col) >> 1] = pack_h2(oc[nt][0]*i0, oc[nt][1]*i0);
        HO[(o1 + col) >> 1] = pack_h2(oc[nt][2]*i1, oc[nt][3]*i1);
    }
}

// ---------------------------------------------------------------------------
// Launch
// ---------------------------------------------------------------------------
extern "C" void kernel_launch(void* const* d_in, const int* in_sizes, int n_in,
                              void* d_out, int out_size)
{
    const float* x    = (const float*)d_in[0];
    const float* cosb = (const float*)d_in[1];
    const float* sinb = (const float*)d_in[2];
    const float* Wq = (const float*)d_in[4];
    const float* bq = (const float*)d_in[5];
    const float* Wk = (const float*)d_in[6];
    const float* bk = (const float*)d_in[7];
    const float* Wv = (const float*)d_in[8];
    const float* bv = (const float*)d_in[9];
    const float* Wo = (const float*)d_in[10];
    const float* bo = (const float*)d_in[11];
    float* out = (float*)d_out;

    __half *xh, *ah, *wh, *wl, *qh, *kh, *kl, *vth, *vtl;
    cudaGetSymbolAddress((void**)&xh,  g_xh);
    cudaGetSymbolAddress((void**)&ah,  g_ah);
    cudaGetSymbolAddress((void**)&wh,  g_wh);
    cudaGetSymbolAddress((void**)&wl,  g_wl);
    cudaGetSymbolAddress((void**)&qh,  g_qh);
    cudaGetSymbolAddress((void**)&kh,  g_kh2);
    cudaGetSymbolAddress((void**)&kl,  g_kl2);
    cudaGetSymbolAddress((void**)&vth, g_vth2);
    cudaGetSymbolAddress((void**)&vtl, g_vtl2);

    cudaFuncSetAttribute(gemm_qkv_kernel,
                         cudaFuncAttributeMaxDynamicSharedMemorySize, GEMM_SMEM);
    cudaFuncSetAttribute(gemm_out_kernel,
                         cudaFuncAttributeMaxDynamicSharedMemorySize, GEMM_SMEM);
    cudaFuncSetAttribute(attn_f16_kernel,
                         cudaFuncAttributeMaxDynamicSharedMemorySize, ATTN_SMEM);

    split_all_kernel<<<SPLIT_BLOCKS, 256>>>(x, Wq, Wk, Wv, Wo, xh, wh, wl);
    gemm_qkv_kernel<<<dim3(DD/128, BS/128, 3), 256, GEMM_SMEM>>>(
        xh, wh, wl, bq, bk, bv, cosb, sinb,
        qh, kh, kl, vth, vtl);
    attn_f16_kernel<<<dim3(SS/64, BB*HH), 128, ATTN_SMEM>>>(
        qh, kh, kl, vth, vtl, ah);
    gemm_out_kernel<<<dim3(DD/128, BS/128), 256, GEMM_SMEM>>>(
        ah, wh + 3*(size_t)NW, wl + 3*(size_t)NW, bo, out);
}

// round 16
// speedup vs baseline: 1.6863x; 1.1967x over previous
#include <cuda_runtime.h>
#include <cuda_bf16.h>
#include <cuda_fp16.h>
#include <stdint.h>

// Problem constants
#define BB 4
#define SS 2048
#define DD 1024
#define HH 16
#define HD 64
#define BS (BB*SS)
#define NQ (BB*HH*SS*HD)
#define NX (BS*DD)
#define NW (DD*DD)

// ---------------------------------------------------------------------------
// Static device scratch
// ---------------------------------------------------------------------------
__device__ __half g_xh[NX];                           // x fp16 single
__device__ __half g_ah[NX];                           // attention out fp16 single
__device__ __half g_wh[4][NW], g_wl[4][NW];           // weights fp16 hi/lo
__device__ __half g_qh[NQ];                           // Q fp16 single [B,H,S,HD]
__device__ __half g_kh2[NQ];                          // K fp16 single [B,H,S,HD]
__device__ __half g_vth2[NQ];                         // V fp16 single [B,H,HD,S]

// ---------------------------------------------------------------------------
// helpers
// ---------------------------------------------------------------------------
__device__ __forceinline__ uint32_t pack_h2(float a, float b) {
    __half ha = __float2half_rn(a), hb = __float2half_rn(b);
    unsigned short ua = *reinterpret_cast<unsigned short*>(&ha);
    unsigned short ub = *reinterpret_cast<unsigned short*>(&hb);
    return (uint32_t)ua | ((uint32_t)ub << 16);
}
__device__ __forceinline__ float h_res(float x) {
    return x - __half2float(__float2half_rn(x));
}

__device__ __forceinline__ void mma_f16(float* c, const uint32_t* a,
                                        uint32_t b0, uint32_t b1)
{
    asm("mma.sync.aligned.m16n8k16.row.col.f32.f16.f16.f32 "
        "{%0,%1,%2,%3},{%4,%5,%6,%7},{%8,%9},{%0,%1,%2,%3};"
        : "+f"(c[0]), "+f"(c[1]), "+f"(c[2]), "+f"(c[3])
        : "r"(a[0]), "r"(a[1]), "r"(a[2]), "r"(a[3]), "r"(b0), "r"(b1));
}

__device__ __forceinline__ void ldsm_x4(uint32_t* r, uint32_t addr) {
    asm volatile("ldmatrix.sync.aligned.m8n8.x4.shared.b16 {%0,%1,%2,%3}, [%4];"
        : "=r"(r[0]), "=r"(r[1]), "=r"(r[2]), "=r"(r[3]) : "r"(addr));
}

#define CP16(dst_smem_u32, src_gptr) \
    asm volatile("cp.async.cg.shared.global [%0], [%1], 16;\n" \
                 :: "r"(dst_smem_u32), "l"(src_gptr))
#define CP_COMMIT() asm volatile("cp.async.commit_group;\n")
#define CP_WAIT1()  asm volatile("cp.async.wait_group 1;\n")
#define CP_WAIT0()  asm volatile("cp.async.wait_group 0;\n")

// ---------------------------------------------------------------------------
// merged split: x -> fp16 single; 4 weights -> fp16 hi/lo
// ---------------------------------------------------------------------------
__global__ __launch_bounds__(256) void split_all_kernel(
    const float* __restrict__ x,
    const float* __restrict__ W0, const float* __restrict__ W1,
    const float* __restrict__ W2, const float* __restrict__ W3,
    __half* __restrict__ xh, __half* __restrict__ wh, __half* __restrict__ wl)
{
    const int gi = blockIdx.x * 256 + threadIdx.x;   // < NX/4 + NW
    if (gi < NX/4) {
        float4 v = ((const float4*)x)[gi];
        ((uint2*)xh)[gi] = make_uint2(pack_h2(v.x, v.y), pack_h2(v.z, v.w));
    } else {
        const int wi = gi - NX/4;
        const int z  = wi >> 18;             // / (NW/4 = 262144)
        const int j  = wi & 262143;
        const float* src = (z == 0) ? W0 : (z == 1) ? W1 : (z == 2) ? W2 : W3;
        float4 v = ((const float4*)src)[j];
        const size_t o = (size_t)z * (NW/4) + j;
        ((uint2*)wh)[o] = make_uint2(pack_h2(v.x, v.y), pack_h2(v.z, v.w));
        ((uint2*)wl)[o] = make_uint2(pack_h2(h_res(v.x), h_res(v.y)),
                                     pack_h2(h_res(v.z), h_res(v.w)));
    }
}
#define SPLIT_BLOCKS ((NX/4 + NW) / 256)     // 12288

// ---------------------------------------------------------------------------
// fp16x2 GEMM mainloop (proven): A single x W hi/lo, 2 MMAs per k16.
// ---------------------------------------------------------------------------
#define RST 20
#define OPB (128*RST)
#define STGU (3*OPB)
#define GEMM_SMEM (2*STGU*4)     // 61440 B

__device__ __forceinline__ void gemm_mainloop(
    const __half* __restrict__ Ah,
    const __half* __restrict__ Wh, const __half* __restrict__ Wl,
    int m0, int n0, uint32_t smb, int tid, float acc[2][8][4])
{
    const int lane = tid & 31;
    const int w    = tid >> 5;
    const int wm   = (w & 3) * 32;
    const int wn   = (w >> 2) * 64;
    const uint32_t aoff = (uint32_t)(((((lane>>3)&1)*8 + (lane&7))*RST + ((lane>>4)*4)) * 4);
    const uint32_t boff = (uint32_t)((((lane>>4)*8 + (lane&7))*RST + (((lane>>3)&1)*4)) * 4);

    const int NK = DD / 32;

    #define LOAD_STAGE(kt, stg) do {                                          \
        uint32_t sb_ = smb + (stg)*STGU*4;                                    \
        _Pragma("unroll")                                                     \
        for (int i_ = 0; i_ < 2; i_++) {                                      \
            int c_ = tid + 256*i_;                                            \
            int row_ = c_ >> 2, c16_ = c_ & 3;                                \
            uint32_t so_ = sb_ + (uint32_t)((row_*RST + c16_*4)*4);           \
            size_t ga_ = (size_t)(m0+row_)*DD + (kt)*32 + c16_*8;             \
            size_t gw_ = (size_t)(n0+row_)*DD + (kt)*32 + c16_*8;             \
            CP16(so_,           Ah + ga_);                                    \
            CP16(so_ + OPB*4,   Wh + gw_);                                    \
            CP16(so_ + 2*OPB*4, Wl + gw_);                                    \
        }                                                                     \
        CP_COMMIT();                                                          \
    } while (0)

    LOAD_STAGE(0, 0);

    for (int it = 0; it < NK; it++) {
        CP_WAIT0();
        __syncthreads();
        if (it + 1 < NK)
            LOAD_STAGE(it + 1, (it + 1) & 1);

        const uint32_t sb  = smb + (it & 1)*STGU*4;
        const uint32_t ahB = sb;
        const uint32_t whB = sb + OPB*4;
        const uint32_t wlB = sb + 2*OPB*4;

        #pragma unroll
        for (int s16 = 0; s16 < 2; s16++) {
            const uint32_t kbyte = s16 * 32;
            uint32_t ah[2][4];
            #pragma unroll
            for (int mt = 0; mt < 2; mt++) {
                const uint32_t ro = (uint32_t)((wm + mt*16)*RST*4);
                ldsm_x4(ah[mt], ahB + aoff + ro + kbyte);
            }
            #pragma unroll
            for (int ntp = 0; ntp < 4; ntp++) {
                const uint32_t ro = (uint32_t)((wn + ntp*16)*RST*4);
                uint32_t wh4[4], wl4[4];
                ldsm_x4(wh4, whB + boff + ro + kbyte);
                ldsm_x4(wl4, wlB + boff + ro + kbyte);
                #pragma unroll
                for (int j = 0; j < 2; j++) {
                    const int nt = 2*ntp + j;
                    #pragma unroll
                    for (int mt = 0; mt < 2; mt++) {
                        mma_f16(acc[mt][nt], ah[mt], wh4[2*j], wh4[2*j+1]);
                        mma_f16(acc[mt][nt], ah[mt], wl4[2*j], wl4[2*j+1]);
                    }
                }
            }
        }
    }
    #undef LOAD_STAGE
}

// ---------------------------------------------------------------------------
// QKV merged GEMM: z=0: Q rope -> fp16 single; z=1: K rope -> fp16 single;
// z=2: V transpose -> fp16 single
// ---------------------------------------------------------------------------
__global__ __launch_bounds__(256, 2) void gemm_qkv_kernel(
    const __half* __restrict__ Ah,
    const __half* __restrict__ whAll, const __half* __restrict__ wlAll,
    const float* __restrict__ bq, const float* __restrict__ bk,
    const float* __restrict__ bv,
    const float* __restrict__ cosb, const float* __restrict__ sinb,
    __half* __restrict__ Qh, __half* __restrict__ Kh,
    __half* __restrict__ Vth)
{
    extern __shared__ uint32_t su[];
    const uint32_t smb = (uint32_t)__cvta_generic_to_shared(su);
    const int tid = threadIdx.x;
    const int m0  = blockIdx.y * 128;
    const int n0  = blockIdx.x * 128;
    const int z   = blockIdx.z;

    const __half* Wh = whAll + (size_t)z * NW;
    const __half* Wl = wlAll + (size_t)z * NW;
    const float* bias = (z == 0) ? bq : (z == 1) ? bk : bv;

    float acc[2][8][4];
    #pragma unroll
    for (int mt = 0; mt < 2; mt++)
        #pragma unroll
        for (int nt = 0; nt < 8; nt++)
            #pragma unroll
            for (int r = 0; r < 4; r++) acc[mt][nt][r] = 0.f;

    gemm_mainloop(Ah, Wh, Wl, m0, n0, smb, tid, acc);

    const int lane = tid & 31;
    const int w    = tid >> 5;
    const int g    = lane >> 2;
    const int q    = lane & 3;
    const int wm   = (w & 3) * 32;
    const int wn   = (w >> 2) * 64;

    if (z < 2) {
        uint32_t* HI = (z == 0) ? (uint32_t*)Qh : (uint32_t*)Kh;
        #pragma unroll
        for (int mt = 0; mt < 2; mt++) {
            const int row0 = m0 + wm + mt*16 + g;
            #pragma unroll
            for (int nt = 0; nt < 4; nt++) {
                const int col = n0 + wn + nt*8 + 2*q;
                const int d = col & 63, h = col >> 6;
                const float bi10 = bias[col],    bi11 = bias[col+1];
                const float bi20 = bias[col+32], bi21 = bias[col+33];
                #pragma unroll
                for (int r2 = 0; r2 < 2; r2++) {
                    const int row = row0 + r2*8;
                    const int b_ = row >> 11, s_ = row & 2047;
                    const float2 cs1 = *(const float2*)&cosb[s_*HD + d];
                    const float2 sn1 = *(const float2*)&sinb[s_*HD + d];
                    const float2 cs2 = *(const float2*)&cosb[s_*HD + d + 32];
                    const float2 sn2 = *(const float2*)&sinb[s_*HD + d + 32];
                    const float x10 = acc[mt][nt  ][r2*2+0] + bi10;
                    const float x11 = acc[mt][nt  ][r2*2+1] + bi11;
                    const float x20 = acc[mt][nt+4][r2*2+0] + bi20;
                    const float x21 = acc[mt][nt+4][r2*2+1] + bi21;
                    const float o10 = x10*cs1.x - x20*sn1.x;
                    const float o11 = x11*cs1.y - x21*sn1.y;
                    const float o20 = x20*cs2.x + x10*sn2.x;
                    const float o21 = x21*cs2.y + x11*sn2.y;
                    const size_t base = (((size_t)b_*HH + h)*SS + s_)*HD;
                    HI[(base + d     ) >> 1] = pack_h2(o10, o11);
                    HI[(base + d + 32) >> 1] = pack_h2(o20, o21);
                }
            }
        }
    } else {
        // V: direct transposed fp16 single write [B,H,HD,S]
        #pragma unroll
        for (int mt = 0; mt < 2; mt++) {
            const int row0 = m0 + wm + mt*16 + g;
            #pragma unroll
            for (int nt = 0; nt < 8; nt++) {
                const int col = n0 + wn + nt*8 + 2*q;
                const int h = col >> 6, d = col & 63;
                const float b0 = bias[col], b1 = bias[col+1];
                #pragma unroll
                for (int r2 = 0; r2 < 2; r2++) {
                    const int row = row0 + r2*8;
                    const int b_ = row >> 11, s_ = row & 2047;
                    const float v0 = acc[mt][nt][r2*2+0] + b0;
                    const float v1 = acc[mt][nt][r2*2+1] + b1;
                    const size_t base0 = (((size_t)b_*HH + h)*HD + d)*SS + s_;
                    Vth[base0]      = __float2half_rn(v0);
                    Vth[base0 + SS] = __float2half_rn(v1);
                }
            }
        }
    }
}

// ---------------------------------------------------------------------------
// Output-projection GEMM: fp32 out [M,N]
// ---------------------------------------------------------------------------
__global__ __launch_bounds__(256, 2) void gemm_out_kernel(
    const __half* __restrict__ Ah,
    const __half* __restrict__ Wh, const __half* __restrict__ Wl,
    const float* __restrict__ bias, float* __restrict__ Cf)
{
    extern __shared__ uint32_t su[];
    const uint32_t smb = (uint32_t)__cvta_generic_to_shared(su);
    const int tid = threadIdx.x;
    const int m0  = blockIdx.y * 128;
    const int n0  = blockIdx.x * 128;

    float acc[2][8][4];
    #pragma unroll
    for (int mt = 0; mt < 2; mt++)
        #pragma unroll
        for (int nt = 0; nt < 8; nt++)
            #pragma unroll
            for (int r = 0; r < 4; r++) acc[mt][nt][r] = 0.f;

    gemm_mainloop(Ah, Wh, Wl, m0, n0, smb, tid, acc);

    const int lane = tid & 31;
    const int w    = tid >> 5;
    const int g    = lane >> 2;
    const int q    = lane & 3;
    const int wm   = (w & 3) * 32;
    const int wn   = (w >> 2) * 64;

    #pragma unroll
    for (int mt = 0; mt < 2; mt++) {
        const int row0 = m0 + wm + mt*16 + g;
        const int row1 = row0 + 8;
        #pragma unroll
        for (int nt = 0; nt < 8; nt++) {
            const int col = n0 + wn + nt*8 + 2*q;
            const float b0 = bias[col], b1 = bias[col + 1];
            *(float2*)&Cf[(size_t)row0*DD + col] =
                make_float2(acc[mt][nt][0] + b0, acc[mt][nt][1] + b1);
            *(float2*)&Cf[(size_t)row1*DD + col] =
                make_float2(acc[mt][nt][2] + b0, acc[mt][nt][3] + b1);
        }
    }
}

// ---------------------------------------------------------------------------
// FlashAttention-2 (causal), pure fp16 single: scores = Q x K (1 MMA/k16),
// PV = P x V (1 MMA/k16). 128 threads, 64-row q-tiles, cp.async dbuf.
// Stage = {K, V} singles: 18432 B/stage, 36864 B total.
// ---------------------------------------------------------------------------
#define KST 36
#define ATILE (64*KST)
#define ASTG  (2*ATILE)          // {K, V}
#define ATTN_SMEM (2*ASTG*4)     // 36864 B

__device__ __forceinline__ void attn_prefetch(
    uint32_t sstage,
    const __half* __restrict__ Kh, const __half* __restrict__ Vth,
    size_t hb, int bh, int k0, int tid)
{
    #pragma unroll
    for (int i = 0; i < 4; i++) {
        int c = tid + 128*i;
        int row = c >> 3, c16 = c & 7;
        uint32_t so = sstage + (uint32_t)((row*KST + c16*4)*4);
        size_t ko = hb + (size_t)(k0 + row)*HD + c16*8;
        CP16(so, Kh + ko);
        size_t vo = ((size_t)bh*HD + row)*SS + k0 + c16*8;
        CP16(so + ATILE*4, Vth + vo);
    }
    CP_COMMIT();
}

__global__ __launch_bounds__(128) void attn_f16_kernel(
    const __half* __restrict__ Qh, const __half* __restrict__ Kh,
    const __half* __restrict__ Vth, __half* __restrict__ OutH)
{
    extern __shared__ uint32_t su[];
    const uint32_t smb = (uint32_t)__cvta_generic_to_shared(su);

    const int tid  = threadIdx.x;
    const int w    = tid >> 5;
    const int lane = tid & 31;
    const int g    = lane >> 2;
    const int q    = lane & 3;
    const int qt   = (SS/64 - 1) - blockIdx.x;
    const int bh   = blockIdx.y;
    const int q0   = qt * 64;
    const size_t hb = (size_t)bh * SS * HD;

    const uint32_t aoff = (uint32_t)(((((lane>>3)&1)*8 + (lane&7))*KST + ((lane>>4)*4)) * 4);
    const uint32_t boff = (uint32_t)((((lane>>4)*8 + (lane&7))*KST + (((lane>>3)&1)*4)) * 4);

    // stage Q into stage1's K area via cp.async
    #pragma unroll
    for (int i = 0; i < 4; i++) {
        int c = tid + 128*i;
        int row = c >> 3, c16 = c & 7;
        uint32_t so = smb + ASTG*4 + (uint32_t)((row*KST + c16*4)*4);
        size_t go = hb + (size_t)(q0 + row)*HD + c16*8;
        CP16(so, Qh + go);
    }
    CP_COMMIT();
    attn_prefetch(smb, Kh, Vth, hb, bh, 0, tid);

    CP_WAIT1();
    __syncthreads();

    const int rb = 16*w;
    uint32_t rQ[4][4];
    #pragma unroll
    for (int ks = 0; ks < 4; ks++) {
        const uint32_t ro = (uint32_t)(rb*KST*4) + ks*32;
        ldsm_x4(rQ[ks], smb + ASTG*4 + aoff + ro);
    }
    __syncthreads();
    if (qt > 0)
        attn_prefetch(smb + ASTG*4, Kh, Vth, hb, bh, 64, tid);

    float oc[8][4];
    #pragma unroll
    for (int nt = 0; nt < 8; nt++)
        #pragma unroll
        for (int r = 0; r < 4; r++) oc[nt][r] = 0.f;
    float m0 = -1e30f, m1 = -1e30f, l0 = 0.f, l1 = 0.f;

    const int row0g = q0 + 16*w + g;
    const int row1g = row0g + 8;

    for (int kt = 0; kt <= qt; kt++) {
        const int k0 = kt * 64;
        const uint32_t ab   = smb + (kt & 1)*ASTG*4;
        const uint32_t aKs  = ab;
        const uint32_t aVs  = ab + ATILE*4;

        if (kt < qt) { CP_WAIT1(); } else { CP_WAIT0(); }
        __syncthreads();

        float sc[8][4];
        #pragma unroll
        for (int nt = 0; nt < 8; nt++)
            #pragma unroll
            for (int r = 0; r < 4; r++) sc[nt][r] = 0.f;

        // scores: Q x K, 1 MMA per (ks, acc)
        #pragma unroll
        for (int ks = 0; ks < 4; ks++) {
            const uint32_t kbyte = ks*32;
            #pragma unroll
            for (int ntp = 0; ntp < 4; ntp++) {
                const uint32_t ro = (uint32_t)(ntp*16*KST*4) + kbyte;
                uint32_t k4[4];
                ldsm_x4(k4, aKs + boff + ro);
                mma_f16(sc[2*ntp  ], rQ[ks], k4[0], k4[1]);
                mma_f16(sc[2*ntp+1], rQ[ks], k4[2], k4[3]);
            }
        }

        const float scale2 = 0.18033688f;   // 0.125 * log2(e)
        const bool diag = (kt == qt);
        #pragma unroll
        for (int nt = 0; nt < 8; nt++) {
            const int colb = k0 + nt*8 + 2*q;
            #pragma unroll
            for (int j = 0; j < 2; j++) {
                float v0 = sc[nt][j]   * scale2;
                float v1 = sc[nt][2+j] * scale2;
                if (diag && (colb + j) > row0g) v0 = -1e30f;
                if (diag && (colb + j) > row1g) v1 = -1e30f;
                sc[nt][j]   = v0;
                sc[nt][2+j] = v1;
            }
        }

        float mx0 = -1e30f, mx1 = -1e30f;
        #pragma unroll
        for (int nt = 0; nt < 8; nt++) {
            mx0 = fmaxf(mx0, fmaxf(sc[nt][0], sc[nt][1]));
            mx1 = fmaxf(mx1, fmaxf(sc[nt][2], sc[nt][3]));
        }
        mx0 = fmaxf(mx0, __shfl_xor_sync(0xffffffffu, mx0, 1));
        mx0 = fmaxf(mx0, __shfl_xor_sync(0xffffffffu, mx0, 2));
        mx1 = fmaxf(mx1, __shfl_xor_sync(0xffffffffu, mx1, 1));
        mx1 = fmaxf(mx1, __shfl_xor_sync(0xffffffffu, mx1, 2));
        const float mn0 = fmaxf(m0, mx0);
        const float mn1 = fmaxf(m1, mx1);
        const float a0 = exp2f(m0 - mn0);
        const float a1 = exp2f(m1 - mn1);
        m0 = mn0; m1 = mn1;

        uint32_t ph[8][2];
        float s0 = 0.f, s1 = 0.f;
        #pragma unroll
        for (int nt = 0; nt < 8; nt++) {
            float p00 = exp2f(sc[nt][0] - mn0);
            float p01 = exp2f(sc[nt][1] - mn0);
            float p10 = exp2f(sc[nt][2] - mn1);
            float p11 = exp2f(sc[nt][3] - mn1);
            s0 += p00 + p01;
            s1 += p10 + p11;
            ph[nt][0] = pack_h2(p00, p01);
            ph[nt][1] = pack_h2(p10, p11);
        }
        s0 += __shfl_xor_sync(0xffffffffu, s0, 1);
        s0 += __shfl_xor_sync(0xffffffffu, s0, 2);
        s1 += __shfl_xor_sync(0xffffffffu, s1, 1);
        s1 += __shfl_xor_sync(0xffffffffu, s1, 2);
        l0 = l0*a0 + s0;
        l1 = l1*a1 + s1;
        #pragma unroll
        for (int nt = 0; nt < 8; nt++) {
            oc[nt][0] *= a0; oc[nt][1] *= a0;
            oc[nt][2] *= a1; oc[nt][3] *= a1;
        }

        // PV: P x V, 1 MMA per (kc, acc)
        #pragma unroll
        for (int kc = 0; kc < 4; kc++) {
            uint32_t ah4[4] = { ph[2*kc][0], ph[2*kc][1], ph[2*kc+1][0], ph[2*kc+1][1] };
            const uint32_t kbyte = kc*32;
            #pragma unroll
            for (int ntp = 0; ntp < 4; ntp++) {
                const uint32_t ro = (uint32_t)(ntp*16*KST*4) + kbyte;
                uint32_t v4[4];
                ldsm_x4(v4, aVs + boff + ro);
                mma_f16(oc[2*ntp  ], ah4, v4[0], v4[1]);
                mma_f16(oc[2*ntp+1], ah4, v4[2], v4[3]);
            }
        }

        __syncthreads();
        if (kt + 2 <= qt)
            attn_prefetch(ab, Kh, Vth, hb, bh, (kt + 2)*64, tid);
    }

    // epilogue: normalize + write fp16 single [B,S,D]
    const float i0 = 1.f / l0;
    const float i1 = 1.f / l1;
    const int b = bh >> 4;
    const int h = bh & 15;
    const size_t o0 = ((size_t)(b*SS + row0g))*DD + h*HD;
    const size_t o1 = ((size_t)(b*SS + row1g))*DD + h*HD;
    uint32_t* HO = (uint32_t*)OutH;
    #pragma unroll
    for (int nt = 0; nt < 8; nt++) {
        const int col = nt*8 + 2*q;
        HO[(o0 + col) >> 1] = pack_h2(oc[nt][0]*i0, oc[nt][1]*i0);
        HO[(o1 + col) >> 1] = pack_h2(oc[nt][2]*i1, oc[nt][3]*i1);
    }
}

// ---------------------------------------------------------------------------
// Launch
// ---------------------------------------------------------------------------
extern "C" void kernel_launch(void* const* d_in, const int* in_sizes, int n_in,
                              void* d_out, int out_size)
{
    const float* x    = (const float*)d_in[0];
    const float* cosb = (const float*)d_in[1];
    const float* sinb = (const float*)d_in[2];
    const float* Wq = (const float*)d_in[4];
    const float* bq = (const float*)d_in[5];
    const float* Wk = (const float*)d_in[6];
    const float* bk = (const float*)d_in[7];
    const float* Wv = (const float*)d_in[8];
    const float* bv = (const float*)d_in[9];
    const float* Wo = (const float*)d_in[10];
    const float* bo = (const float*)d_in[11];
    float* out = (float*)d_out;

    __half *xh, *ah, *wh, *wl, *qh, *kh, *vth;
    cudaGetSymbolAddress((void**)&xh,  g_xh);
    cudaGetSymbolAddress((void**)&ah,  g_ah);
    cudaGetSymbolAddress((void**)&wh,  g_wh);
    cudaGetSymbolAddress((void**)&wl,  g_wl);
    cudaGetSymbolAddress((void**)&qh,  g_qh);
    cudaGetSymbolAddress((void**)&kh,  g_kh2);
    cudaGetSymbolAddress((void**)&vth, g_vth2);

    cudaFuncSetAttribute(gemm_qkv_kernel,
                         cudaFuncAttributeMaxDynamicSharedMemorySize, GEMM_SMEM);
    cudaFuncSetAttribute(gemm_out_kernel,
                         cudaFuncAttributeMaxDynamicSharedMemorySize, GEMM_SMEM);
    cudaFuncSetAttribute(attn_f16_kernel,
                         cudaFuncAttributeMaxDynamicSharedMemorySize, ATTN_SMEM);

    split_all_kernel<<<SPLIT_BLOCKS, 256>>>(x, Wq, Wk, Wv, Wo, xh, wh, wl);
    gemm_qkv_kernel<<<dim3(DD/128, BS/128, 3), 256, GEMM_SMEM>>>(
        xh, wh, wl, bq, bk, bv, cosb, sinb, qh, kh, vth);
    attn_f16_kernel<<<dim3(SS/64, BB*HH), 128, ATTN_SMEM>>>(
        qh, kh, vth, ah);
    gemm_out_kernel<<<dim3(DD/128, BS/128), 256, GEMM_SMEM>>>(
        ah, wh + 3*(size_t)NW, wl + 3*(size_t)NW, bo, out);
}

// round 17
// speedup vs baseline: 2.3861x; 1.4150x over previous
#include <cuda_runtime.h>
#include <cuda_bf16.h>
#include <cuda_fp16.h>
#include <stdint.h>

// Problem constants
#define BB 4
#define SS 2048
#define DD 1024
#define HH 16
#define HD 64
#define BS (BB*SS)
#define NQ (BB*HH*SS*HD)
#define NX (BS*DD)
#define NW (DD*DD)

// ---------------------------------------------------------------------------
// Static device scratch
// ---------------------------------------------------------------------------
__device__ __half g_xh[NX];                           // x fp16 single
__device__ __half g_ah[NX];                           // attention out fp16 single
__device__ __half g_wh[4][NW];                        // weights fp16 single
__device__ __half g_qh[NQ];                           // Q fp16 single [B,H,S,HD]
__device__ __half g_kh2[NQ];                          // K fp16 single [B,H,S,HD]
__device__ __half g_vth2[NQ];                         // V fp16 single [B,H,HD,S]

// ---------------------------------------------------------------------------
// helpers
// ---------------------------------------------------------------------------
__device__ __forceinline__ uint32_t pack_h2(float a, float b) {
    __half ha = __float2half_rn(a), hb = __float2half_rn(b);
    unsigned short ua = *reinterpret_cast<unsigned short*>(&ha);
    unsigned short ub = *reinterpret_cast<unsigned short*>(&hb);
    return (uint32_t)ua | ((uint32_t)ub << 16);
}

__device__ __forceinline__ void mma_f16(float* c, const uint32_t* a,
                                        uint32_t b0, uint32_t b1)
{
    asm("mma.sync.aligned.m16n8k16.row.col.f32.f16.f16.f32 "
        "{%0,%1,%2,%3},{%4,%5,%6,%7},{%8,%9},{%0,%1,%2,%3};"
        : "+f"(c[0]), "+f"(c[1]), "+f"(c[2]), "+f"(c[3])
        : "r"(a[0]), "r"(a[1]), "r"(a[2]), "r"(a[3]), "r"(b0), "r"(b1));
}

__device__ __forceinline__ void ldsm_x4(uint32_t* r, uint32_t addr) {
    asm volatile("ldmatrix.sync.aligned.m8n8.x4.shared.b16 {%0,%1,%2,%3}, [%4];"
        : "=r"(r[0]), "=r"(r[1]), "=r"(r[2]), "=r"(r[3]) : "r"(addr));
}

#define CP16(dst_smem_u32, src_gptr) \
    asm volatile("cp.async.cg.shared.global [%0], [%1], 16;\n" \
                 :: "r"(dst_smem_u32), "l"(src_gptr))
#define CP_COMMIT() asm volatile("cp.async.commit_group;\n")
#define CP_WAIT1()  asm volatile("cp.async.wait_group 1;\n")
#define CP_WAIT0()  asm volatile("cp.async.wait_group 0;\n")

// ---------------------------------------------------------------------------
// merged split: x -> fp16 single; 4 weights -> fp16 single
// ---------------------------------------------------------------------------
__global__ __launch_bounds__(256) void split_all_kernel(
    const float* __restrict__ x,
    const float* __restrict__ W0, const float* __restrict__ W1,
    const float* __restrict__ W2, const float* __restrict__ W3,
    __half* __restrict__ xh, __half* __restrict__ wh)
{
    const int gi = blockIdx.x * 256 + threadIdx.x;   // < NX/4 + NW
    if (gi < NX/4) {
        float4 v = ((const float4*)x)[gi];
        ((uint2*)xh)[gi] = make_uint2(pack_h2(v.x, v.y), pack_h2(v.z, v.w));
    } else {
        const int wi = gi - NX/4;
        const int z  = wi >> 18;             // / (NW/4 = 262144)
        const int j  = wi & 262143;
        const float* src = (z == 0) ? W0 : (z == 1) ? W1 : (z == 2) ? W2 : W3;
        float4 v = ((const float4*)src)[j];
        const size_t o = (size_t)z * (NW/4) + j;
        ((uint2*)wh)[o] = make_uint2(pack_h2(v.x, v.y), pack_h2(v.z, v.w));
    }
}
#define SPLIT_BLOCKS ((NX/4 + NW) / 256)     // 12288

// ---------------------------------------------------------------------------
// fp16 single GEMM mainloop: A single x W single, 1 MMA per k16 per acc.
// 128x128 tile, BK=32, 256 thr, single barrier per K-iteration.
// ---------------------------------------------------------------------------
#define RST 20
#define OPB (128*RST)
#define STGU (2*OPB)             // A + W
#define GEMM_SMEM (2*STGU*4)     // 40960 B

__device__ __forceinline__ void gemm_mainloop(
    const __half* __restrict__ Ah, const __half* __restrict__ Wh,
    int m0, int n0, uint32_t smb, int tid, float acc[2][8][4])
{
    const int lane = tid & 31;
    const int w    = tid >> 5;
    const int wm   = (w & 3) * 32;
    const int wn   = (w >> 2) * 64;
    const uint32_t aoff = (uint32_t)(((((lane>>3)&1)*8 + (lane&7))*RST + ((lane>>4)*4)) * 4);
    const uint32_t boff = (uint32_t)((((lane>>4)*8 + (lane&7))*RST + (((lane>>3)&1)*4)) * 4);

    const int NK = DD / 32;

    #define LOAD_STAGE(kt, stg) do {                                          \
        uint32_t sb_ = smb + (stg)*STGU*4;                                    \
        _Pragma("unroll")                                                     \
        for (int i_ = 0; i_ < 2; i_++) {                                      \
            int c_ = tid + 256*i_;                                            \
            int row_ = c_ >> 2, c16_ = c_ & 3;                                \
            uint32_t so_ = sb_ + (uint32_t)((row_*RST + c16_*4)*4);           \
            size_t ga_ = (size_t)(m0+row_)*DD + (kt)*32 + c16_*8;             \
            size_t gw_ = (size_t)(n0+row_)*DD + (kt)*32 + c16_*8;             \
            CP16(so_,         Ah + ga_);                                      \
            CP16(so_ + OPB*4, Wh + gw_);                                      \
        }                                                                     \
        CP_COMMIT();                                                          \
    } while (0)

    LOAD_STAGE(0, 0);

    for (int it = 0; it < NK; it++) {
        CP_WAIT0();
        __syncthreads();
        if (it + 1 < NK)
            LOAD_STAGE(it + 1, (it + 1) & 1);

        const uint32_t sb  = smb + (it & 1)*STGU*4;
        const uint32_t ahB = sb;
        const uint32_t whB = sb + OPB*4;

        #pragma unroll
        for (int s16 = 0; s16 < 2; s16++) {
            const uint32_t kbyte = s16 * 32;
            uint32_t ah[2][4];
            #pragma unroll
            for (int mt = 0; mt < 2; mt++) {
                const uint32_t ro = (uint32_t)((wm + mt*16)*RST*4);
                ldsm_x4(ah[mt], ahB + aoff + ro + kbyte);
            }
            #pragma unroll
            for (int ntp = 0; ntp < 4; ntp++) {
                const uint32_t ro = (uint32_t)((wn + ntp*16)*RST*4);
                uint32_t wh4[4];
                ldsm_x4(wh4, whB + boff + ro + kbyte);
                #pragma unroll
                for (int j = 0; j < 2; j++) {
                    const int nt = 2*ntp + j;
                    #pragma unroll
                    for (int mt = 0; mt < 2; mt++)
                        mma_f16(acc[mt][nt], ah[mt], wh4[2*j], wh4[2*j+1]);
                }
            }
        }
    }
    #undef LOAD_STAGE
}

// ---------------------------------------------------------------------------
// QKV merged GEMM: z=0: Q rope; z=1: K rope; z=2: V transpose (all fp16 single)
// ---------------------------------------------------------------------------
__global__ __launch_bounds__(256, 2) void gemm_qkv_kernel(
    const __half* __restrict__ Ah, const __half* __restrict__ whAll,
    const float* __restrict__ bq, const float* __restrict__ bk,
    const float* __restrict__ bv,
    const float* __restrict__ cosb, const float* __restrict__ sinb,
    __half* __restrict__ Qh, __half* __restrict__ Kh,
    __half* __restrict__ Vth)
{
    extern __shared__ uint32_t su[];
    const uint32_t smb = (uint32_t)__cvta_generic_to_shared(su);
    const int tid = threadIdx.x;
    const int m0  = blockIdx.y * 128;
    const int n0  = blockIdx.x * 128;
    const int z   = blockIdx.z;

    const __half* Wh = whAll + (size_t)z * NW;
    const float* bias = (z == 0) ? bq : (z == 1) ? bk : bv;

    float acc[2][8][4];
    #pragma unroll
    for (int mt = 0; mt < 2; mt++)
        #pragma unroll
        for (int nt = 0; nt < 8; nt++)
            #pragma unroll
            for (int r = 0; r < 4; r++) acc[mt][nt][r] = 0.f;

    gemm_mainloop(Ah, Wh, m0, n0, smb, tid, acc);

    const int lane = tid & 31;
    const int w    = tid >> 5;
    const int g    = lane >> 2;
    const int q    = lane & 3;
    const int wm   = (w & 3) * 32;
    const int wn   = (w >> 2) * 64;

    if (z < 2) {
        uint32_t* HI = (z == 0) ? (uint32_t*)Qh : (uint32_t*)Kh;
        #pragma unroll
        for (int mt = 0; mt < 2; mt++) {
            const int row0 = m0 + wm + mt*16 + g;
            #pragma unroll
            for (int nt = 0; nt < 4; nt++) {
                const int col = n0 + wn + nt*8 + 2*q;
                const int d = col & 63, h = col >> 6;
                const float bi10 = bias[col],    bi11 = bias[col+1];
                const float bi20 = bias[col+32], bi21 = bias[col+33];
                #pragma unroll
                for (int r2 = 0; r2 < 2; r2++) {
                    const int row = row0 + r2*8;
                    const int b_ = row >> 11, s_ = row & 2047;
                    const float2 cs1 = *(const float2*)&cosb[s_*HD + d];
                    const float2 sn1 = *(const float2*)&sinb[s_*HD + d];
                    const float2 cs2 = *(const float2*)&cosb[s_*HD + d + 32];
                    const float2 sn2 = *(const float2*)&sinb[s_*HD + d + 32];
                    const float x10 = acc[mt][nt  ][r2*2+0] + bi10;
                    const float x11 = acc[mt][nt  ][r2*2+1] + bi11;
                    const float x20 = acc[mt][nt+4][r2*2+0] + bi20;
                    const float x21 = acc[mt][nt+4][r2*2+1] + bi21;
                    const float o10 = x10*cs1.x - x20*sn1.x;
                    const float o11 = x11*cs1.y - x21*sn1.y;
                    const float o20 = x20*cs2.x + x10*sn2.x;
                    const float o21 = x21*cs2.y + x11*sn2.y;
                    const size_t base = (((size_t)b_*HH + h)*SS + s_)*HD;
                    HI[(base + d     ) >> 1] = pack_h2(o10, o11);
                    HI[(base + d + 32) >> 1] = pack_h2(o20, o21);
                }
            }
        }
    } else {
        // V: direct transposed fp16 single write [B,H,HD,S]
        #pragma unroll
        for (int mt = 0; mt < 2; mt++) {
            const int row0 = m0 + wm + mt*16 + g;
            #pragma unroll
            for (int nt = 0; nt < 8; nt++) {
                const int col = n0 + wn + nt*8 + 2*q;
                const int h = col >> 6, d = col & 63;
                const float b0 = bias[col], b1 = bias[col+1];
                #pragma unroll
                for (int r2 = 0; r2 < 2; r2++) {
                    const int row = row0 + r2*8;
                    const int b_ = row >> 11, s_ = row & 2047;
                    const float v0 = acc[mt][nt][r2*2+0] + b0;
                    const float v1 = acc[mt][nt][r2*2+1] + b1;
                    const size_t base0 = (((size_t)b_*HH + h)*HD + d)*SS + s_;
                    Vth[base0]      = __float2half_rn(v0);
                    Vth[base0 + SS] = __float2half_rn(v1);
                }
            }
        }
    }
}

// ---------------------------------------------------------------------------
// Output-projection GEMM: fp32 out [M,N]
// ---------------------------------------------------------------------------
__global__ __launch_bounds__(256, 2) void gemm_out_kernel(
    const __half* __restrict__ Ah, const __half* __restrict__ Wh,
    const float* __restrict__ bias, float* __restrict__ Cf)
{
    extern __shared__ uint32_t su[];
    const uint32_t smb = (uint32_t)__cvta_generic_to_shared(su);
    const int tid = threadIdx.x;
    const int m0  = blockIdx.y * 128;
    const int n0  = blockIdx.x * 128;

    float acc[2][8][4];
    #pragma unroll
    for (int mt = 0; mt < 2; mt++)
        #pragma unroll
        for (int nt = 0; nt < 8; nt++)
            #pragma unroll
            for (int r = 0; r < 4; r++) acc[mt][nt][r] = 0.f;

    gemm_mainloop(Ah, Wh, m0, n0, smb, tid, acc);

    const int lane = tid & 31;
    const int w    = tid >> 5;
    const int g    = lane >> 2;
    const int q    = lane & 3;
    const int wm   = (w & 3) * 32;
    const int wn   = (w >> 2) * 64;

    #pragma unroll
    for (int mt = 0; mt < 2; mt++) {
        const int row0 = m0 + wm + mt*16 + g;
        const int row1 = row0 + 8;
        #pragma unroll
        for (int nt = 0; nt < 8; nt++) {
            const int col = n0 + wn + nt*8 + 2*q;
            const float b0 = bias[col], b1 = bias[col + 1];
            *(float2*)&Cf[(size_t)row0*DD + col] =
                make_float2(acc[mt][nt][0] + b0, acc[mt][nt][1] + b1);
            *(float2*)&Cf[(size_t)row1*DD + col] =
                make_float2(acc[mt][nt][2] + b0, acc[mt][nt][3] + b1);
        }
    }
}

// ---------------------------------------------------------------------------
// FlashAttention-2 (causal), pure fp16 single (R16 proven kernel).
// ---------------------------------------------------------------------------
#define KST 36
#define ATILE (64*KST)
#define ASTG  (2*ATILE)          // {K, V}
#define ATTN_SMEM (2*ASTG*4)     // 36864 B

__device__ __forceinline__ void attn_prefetch(
    uint32_t sstage,
    const __half* __restrict__ Kh, const __half* __restrict__ Vth,
    size_t hb, int bh, int k0, int tid)
{
    #pragma unroll
    for (int i = 0; i < 4; i++) {
        int c = tid + 128*i;
        int row = c >> 3, c16 = c & 7;
        uint32_t so = sstage + (uint32_t)((row*KST + c16*4)*4);
        size_t ko = hb + (size_t)(k0 + row)*HD + c16*8;
        CP16(so, Kh + ko);
        size_t vo = ((size_t)bh*HD + row)*SS + k0 + c16*8;
        CP16(so + ATILE*4, Vth + vo);
    }
    CP_COMMIT();
}

__global__ __launch_bounds__(128) void attn_f16_kernel(
    const __half* __restrict__ Qh, const __half* __restrict__ Kh,
    const __half* __restrict__ Vth, __half* __restrict__ OutH)
{
    extern __shared__ uint32_t su[];
    const uint32_t smb = (uint32_t)__cvta_generic_to_shared(su);

    const int tid  = threadIdx.x;
    const int w    = tid >> 5;
    const int lane = tid & 31;
    const int g    = lane >> 2;
    const int q    = lane & 3;
    const int qt   = (SS/64 - 1) - blockIdx.x;
    const int bh   = blockIdx.y;
    const int q0   = qt * 64;
    const size_t hb = (size_t)bh * SS * HD;

    const uint32_t aoff = (uint32_t)(((((lane>>3)&1)*8 + (lane&7))*KST + ((lane>>4)*4)) * 4);
    const uint32_t boff = (uint32_t)((((lane>>4)*8 + (lane&7))*KST + (((lane>>3)&1)*4)) * 4);

    // stage Q into stage1's K area via cp.async
    #pragma unroll
    for (int i = 0; i < 4; i++) {
        int c = tid + 128*i;
        int row = c >> 3, c16 = c & 7;
        uint32_t so = smb + ASTG*4 + (uint32_t)((row*KST + c16*4)*4);
        size_t go = hb + (size_t)(q0 + row)*HD + c16*8;
        CP16(so, Qh + go);
    }
    CP_COMMIT();
    attn_prefetch(smb, Kh, Vth, hb, bh, 0, tid);

    CP_WAIT1();
    __syncthreads();

    const int rb = 16*w;
    uint32_t rQ[4][4];
    #pragma unroll
    for (int ks = 0; ks < 4; ks++) {
        const uint32_t ro = (uint32_t)(rb*KST*4) + ks*32;
        ldsm_x4(rQ[ks], smb + ASTG*4 + aoff + ro);
    }
    __syncthreads();
    if (qt > 0)
        attn_prefetch(smb + ASTG*4, Kh, Vth, hb, bh, 64, tid);

    float oc[8][4];
    #pragma unroll
    for (int nt = 0; nt < 8; nt++)
        #pragma unroll
        for (int r = 0; r < 4; r++) oc[nt][r] = 0.f;
    float m0 = -1e30f, m1 = -1e30f, l0 = 0.f, l1 = 0.f;

    const int row0g = q0 + 16*w + g;
    const int row1g = row0g + 8;

    for (int kt = 0; kt <= qt; kt++) {
        const int k0 = kt * 64;
        const uint32_t ab   = smb + (kt & 1)*ASTG*4;
        const uint32_t aKs  = ab;
        const uint32_t aVs  = ab + ATILE*4;

        if (kt < qt) { CP_WAIT1(); } else { CP_WAIT0(); }
        __syncthreads();

        float sc[8][4];
        #pragma unroll
        for (int nt = 0; nt < 8; nt++)
            #pragma unroll
            for (int r = 0; r < 4; r++) sc[nt][r] = 0.f;

        #pragma unroll
        for (int ks = 0; ks < 4; ks++) {
            const uint32_t kbyte = ks*32;
            #pragma unroll
            for (int ntp = 0; ntp < 4; ntp++) {
                const uint32_t ro = (uint32_t)(ntp*16*KST*4) + kbyte;
                uint32_t k4[4];
                ldsm_x4(k4, aKs + boff + ro);
                mma_f16(sc[2*ntp  ], rQ[ks], k4[0], k4[1]);
                mma_f16(sc[2*ntp+1], rQ[ks], k4[2], k4[3]);
            }
        }

        const float scale2 = 0.18033688f;   // 0.125 * log2(e)
        const bool diag = (kt == qt);
        #pragma unroll
        for (int nt = 0; nt < 8; nt++) {
            const int colb = k0 + nt*8 + 2*q;
            #pragma unroll
            for (int j = 0; j < 2; j++) {
                float v0 = sc[nt][j]   * scale2;
                float v1 = sc[nt][2+j] * scale2;
                if (diag && (colb + j) > row0g) v0 = -1e30f;
                if (diag && (colb + j) > row1g) v1 = -1e30f;
                sc[nt][j]   = v0;
                sc[nt][2+j] = v1;
            }
        }

        float mx0 = -1e30f, mx1 = -1e30f;
        #pragma unroll
        for (int nt = 0; nt < 8; nt++) {
            mx0 = fmaxf(mx0, fmaxf(sc[nt][0], sc[nt][1]));
            mx1 = fmaxf(mx1, fmaxf(sc[nt][2], sc[nt][3]));
        }
        mx0 = fmaxf(mx0, __shfl_xor_sync(0xffffffffu, mx0, 1));
        mx0 = fmaxf(mx0, __shfl_xor_sync(0xffffffffu, mx0, 2));
        mx1 = fmaxf(mx1, __shfl_xor_sync(0xffffffffu, mx1, 1));
        mx1 = fmaxf(mx1, __shfl_xor_sync(0xffffffffu, mx1, 2));
        const float mn0 = fmaxf(m0, mx0);
        const float mn1 = fmaxf(m1, mx1);
        const float a0 = exp2f(m0 - mn0);
        const float a1 = exp2f(m1 - mn1);
        m0 = mn0; m1 = mn1;

        uint32_t ph[8][2];
        float s0 = 0.f, s1 = 0.f;
        #pragma unroll
        for (int nt = 0; nt < 8; nt++) {
            float p00 = exp2f(sc[nt][0] - mn0);
            float p01 = exp2f(sc[nt][1] - mn0);
            float p10 = exp2f(sc[nt][2] - mn1);
            float p11 = exp2f(sc[nt][3] - mn1);
            s0 += p00 + p01;
            s1 += p10 + p11;
            ph[nt][0] = pack_h2(p00, p01);
            ph[nt][1] = pack_h2(p10, p11);
        }
        s0 += __shfl_xor_sync(0xffffffffu, s0, 1);
        s0 += __shfl_xor_sync(0xffffffffu, s0, 2);
        s1 += __shfl_xor_sync(0xffffffffu, s1, 1);
        s1 += __shfl_xor_sync(0xffffffffu, s1, 2);
        l0 = l0*a0 + s0;
        l1 = l1*a1 + s1;
        #pragma unroll
        for (int nt = 0; nt < 8; nt++) {
            oc[nt][0] *= a0; oc[nt][1] *= a0;
            oc[nt][2] *= a1; oc[nt][3] *= a1;
        }

        #pragma unroll
        for (int kc = 0; kc < 4; kc++) {
            uint32_t ah4[4] = { ph[2*kc][0], ph[2*kc][1], ph[2*kc+1][0], ph[2*kc+1][1] };
            const uint32_t kbyte = kc*32;
            #pragma unroll
            for (int ntp = 0; ntp < 4; ntp++) {
                const uint32_t ro = (uint32_t)(ntp*16*KST*4) + kbyte;
                uint32_t v4[4];
                ldsm_x4(v4, aVs + boff + ro);
                mma_f16(oc[2*ntp  ], ah4, v4[0], v4[1]);
                mma_f16(oc[2*ntp+1], ah4, v4[2], v4[3]);
            }
        }

        __syncthreads();
        if (kt + 2 <= qt)
            attn_prefetch(ab, Kh, Vth, hb, bh, (kt + 2)*64, tid);
    }

    // epilogue: normalize + write fp16 single [B,S,D]
    const float i0 = 1.f / l0;
    const float i1 = 1.f / l1;
    const int b = bh >> 4;
    const int h = bh & 15;
    const size_t o0 = ((size_t)(b*SS + row0g))*DD + h*HD;
    const size_t o1 = ((size_t)(b*SS + row1g))*DD + h*HD;
    uint32_t* HO = (uint32_t*)OutH;
    #pragma unroll
    for (int nt = 0; nt < 8; nt++) {
        const int col = nt*8 + 2*q;
        HO[(o0 + col) >> 1] = pack_h2(oc[nt][0]*i0, oc[nt][1]*i0);
        HO[(o1 + col) >> 1] = pack_h2(oc[nt][2]*i1, oc[nt][3]*i1);
    }
}

// ---------------------------------------------------------------------------
// Launch
// ---------------------------------------------------------------------------
extern "C" void kernel_launch(void* const* d_in, const int* in_sizes, int n_in,
                              void* d_out, int out_size)
{
    const float* x    = (const float*)d_in[0];
    const float* cosb = (const float*)d_in[1];
    const float* sinb = (const float*)d_in[2];
    const float* Wq = (const float*)d_in[4];
    const float* bq = (const float*)d_in[5];
    const float* Wk = (const float*)d_in[6];
    const float* bk = (const float*)d_in[7];
    const float* Wv = (const float*)d_in[8];
    const float* bv = (const float*)d_in[9];
    const float* Wo = (const float*)d_in[10];
    const float* bo = (const float*)d_in[11];
    float* out = (float*)d_out;

    __half *xh, *ah, *wh, *qh, *kh, *vth;
    cudaGetSymbolAddress((void**)&xh,  g_xh);
    cudaGetSymbolAddress((void**)&ah,  g_ah);
    cudaGetSymbolAddress((void**)&wh,  g_wh);
    cudaGetSymbolAddress((void**)&qh,  g_qh);
    cudaGetSymbolAddress((void**)&kh,  g_kh2);
    cudaGetSymbolAddress((void**)&vth, g_vth2);

    cudaFuncSetAttribute(gemm_qkv_kernel,
                         cudaFuncAttributeMaxDynamicSharedMemorySize, GEMM_SMEM);
    cudaFuncSetAttribute(gemm_out_kernel,
                         cudaFuncAttributeMaxDynamicSharedMemorySize, GEMM_SMEM);
    cudaFuncSetAttribute(attn_f16_kernel,
                         cudaFuncAttributeMaxDynamicSharedMemorySize, ATTN_SMEM);

    split_all_kernel<<<SPLIT_BLOCKS, 256>>>(x, Wq, Wk, Wv, Wo, xh, wh);
    gemm_qkv_kernel<<<dim3(DD/128, BS/128, 3), 256, GEMM_SMEM>>>(
        xh, wh, bq, bk, bv, cosb, sinb, qh, kh, vth);
    attn_f16_kernel<<<dim3(SS/64, BB*HH), 128, ATTN_SMEM>>>(
        qh, kh, vth, ah);
    gemm_out_kernel<<<dim3(DD/128, BS/128), 256, GEMM_SMEM>>>(
        ah, wh + 3*(size_t)NW, bo, out);
}